// round 11
// baseline (speedup 1.0000x reference)
#include <cuda_runtime.h>
#include <cuda_fp16.h>
#include <cstdint>

#define NB    8
#define PPC   1024
#define NPTS  8192
#define KNN   20
#define NEDGE (NPTS*KNN)

// ---------------- scratch (device globals; allocation-free) ----------------
__device__ int   g_nbr[NEDGE];
__device__ __align__(16) float g_h1T[64*NEDGE];    // layer1 out, TRANSPOSED [c][edge]
__device__ __align__(16) float g_y2[NEDGE*128];    // layer2 out (pre-max), row-major
__device__ __align__(16) float g_x1T[128*NPTS];    // after max over K, TRANSPOSED [c][n]
__device__ __align__(16) float g_x3[NPTS*1024];    // layer3 out, row-major
__device__ float g_xg[NB*2048];                    // pooled [max | mean]
__device__ __align__(16) float g_Bp4[38400*40];    // layer4 coeffs [f][o]
__device__ __align__(16) __half g_B1h[64*104];     // layer1 coeffs [o][96k pad104] hi
__device__ __align__(16) __half g_B1l[64*104];     // lo
__device__ __align__(16) __half g_B2[128*1120];    // layer2 coeffs [o][f] fp16
__device__ __align__(16) __half g_B3[1024*2240];   // layer3 coeffs [o][f] fp16
// layer3 basis, materialized once: blocked [ (mt*28+ch) ][128 rows][80 halves]
__device__ __align__(16) __half g_Phi3h[64*28*128*80];
__device__ __align__(16) __half g_Phi3l[64*28*128*80];
__device__ float g_l4p[NB*8*40];

// ---------------- small helpers ----------------
__device__ __forceinline__ uint32_t pack_h2(float lo, float hi) {
    __half2 h = __floats2half2_rn(lo, hi);
    return *(uint32_t*)&h;
}
__device__ __forceinline__ void cp16(uint32_t dst, const void* src) {
    asm volatile("cp.async.cg.shared.global [%0], [%1], 16;" :: "r"(dst), "l"(src));
}
#define CP_COMMIT() asm volatile("cp.async.commit_group;" ::: "memory")
#define CP_WAIT0()  asm volatile("cp.async.wait_group 0;" ::: "memory")

__device__ __forceinline__ void mma_f16(float* c, uint32_t a0, uint32_t a1,
                                        uint32_t a2, uint32_t a3,
                                        uint32_t b0, uint32_t b1) {
    asm volatile(
        "mma.sync.aligned.m16n8k16.row.col.f32.f16.f16.f32 "
        "{%0,%1,%2,%3}, {%4,%5,%6,%7}, {%8,%9}, {%0,%1,%2,%3};\n"
        : "+f"(c[0]), "+f"(c[1]), "+f"(c[2]), "+f"(c[3])
        : "r"(a0), "r"(a1), "r"(a2), "r"(a3), "r"(b0), "r"(b1));
}

// ---------------- packing kernels ----------------
// pack12: layer1 B (hi/lo, padded [64][104]) + layer2 B (fp16 [o][f])
__global__ void pack12(const float* __restrict__ c1, const float* __restrict__ c2) {
    int idx = blockIdx.x * 256 + threadIdx.x;
    if (idx < 64 * 104) {
        int o = idx / 104, jj = idx - o * 104;
        float v = 0.f;
        if (jj < 96) {
            int c = jj >> 4, j = jj & 15;
            if (j < 10) {
                int trig = j & 1, k = j >> 1, w = c / 3, i = c % 3;
                v = c1[(((trig * 64 + o) * 2 + w) * 3 + i) * 5 + k];
            }
        }
        __half h = __float2half_rn(v);
        g_B1h[idx] = h;
        g_B1l[idx] = __float2half_rn(v - __half2float(h));
    } else {
        int id2 = idx - 64 * 104;
        if (id2 < 128 * 1120) {
            int o = id2 / 1120, f = id2 - o * 1120;
            int trig = f & 1, f2 = f >> 1, k = f2 % 5, wi = f2 / 5, w = wi / 16, i = wi - w * 16;
            g_B2[id2] = __float2half_rn(
                c2[((((size_t)trig * 128 + o) * 7 + w) * 16 + i) * 5 + k]);
        }
    }
}

__global__ void pack3(const float* __restrict__ c3) {
    int idx = blockIdx.x * 256 + threadIdx.x;
    if (idx >= 1024 * 2240) return;
    int o = idx / 2240, f = idx - o * 2240;
    int trig = f & 1, f2 = f >> 1, k = f2 % 5, wi = f2 / 5, w = wi / 32, i = wi - w * 32;
    g_B3[idx] = __float2half_rn(
        c3[((((size_t)trig * 1024 + o) * 7 + w) * 32 + i) * 5 + k]);
}

__global__ void pack_coef4(const float* __restrict__ src) {
    const int dout = 40, nw = 15, W = 256, g = 5;
    int idx = blockIdx.x * 256 + threadIdx.x;
    if (idx >= 38400 * 40) return;
    int o = idx % dout;
    int f = idx / dout;
    int trig = f & 1;
    int f2 = f >> 1;
    int k = f2 % g;
    int wi = f2 / g;
    int w = wi / W;
    int i = wi - w * W;
    g_Bp4[idx] = src[((((size_t)trig * dout + o) * nw + w) * W + i) * g + k];
}

// ---------------- kNN: register top-20 per query thread ----------------
__global__ void knn_kernel(const float* __restrict__ pos) {
    __shared__ float sx[PPC], sy[PPC], sz[PPC];
    int tid = threadIdx.x;
    int b   = blockIdx.x >> 2;
    int ql  = ((blockIdx.x & 3) << 8) + tid;
    for (int p = tid; p < PPC; p += 256) {
        const float* pp = pos + (b * PPC + p) * 3;
        sx[p] = pp[0]; sy[p] = pp[1]; sz[p] = pp[2];
    }
    __syncthreads();
    float qx = sx[ql], qy = sy[ql], qz = sz[ql];
    float v[KNN]; int id[KNN];
#pragma unroll
    for (int j = 0; j < KNN; ++j) { v[j] = 1e30f; id[j] = -1; }
    float vmax = 1e30f; int mpos = 0;
    for (int p = 0; p < PPC; ++p) {
        float dx = sx[p] - qx, dy = sy[p] - qy, dz = sz[p] - qz;
        float d = dx * dx + dy * dy + dz * dz;
        if (p == ql) d = 1e30f;
        if (d < vmax) {
#pragma unroll
            for (int j = 0; j < KNN; ++j) if (j == mpos) { v[j] = d; id[j] = p; }
            vmax = v[0]; mpos = 0;
#pragma unroll
            for (int j = 1; j < KNN; ++j) if (v[j] > vmax) { vmax = v[j]; mpos = j; }
        }
    }
    int q = b * PPC + ql;
#pragma unroll
    for (int j = 0; j < KNN; ++j) g_nbr[q * KNN + j] = b * PPC + id[j];
}

// ---------------- layer1 as fused-basis HMMA (fp16x3), M=128/block -----------
// A: [128 rows][6 cols x 16 slots = 96 k, pad 104], B: [64][96 pad 104]
__global__ void __launch_bounds__(256, 2)
layer1_mma(const float* __restrict__ pos, const float* __restrict__ b1) {
    constexpr int SA1 = 104;
    extern __shared__ unsigned char smem[];
    __half* sAh = (__half*)smem;                     // 26624 B
    __half* sAl = (__half*)(smem + 26624);           // 26624 B
    __half* sBh = (__half*)(smem + 53248);           // 13312 B
    __half* sBl = (__half*)(smem + 66560);           // 13312 B
    float*  bs  = (float*)(smem + 79872);            // 256 B
    float*  tr  = (float*)smem;                      // reuse after MMA (33792 B)

    int tid = threadIdx.x, lane = tid & 31, warp = tid >> 5;
    int wm = warp & 3, wn = warp >> 2;
    int qr = lane >> 2, qk = lane & 3;
    int row = tid & 127, cg = tid >> 7;

    // stage B (threads 128-255), bias (threads 0-63)
    if (tid >= 128) {
        int tt = tid - 128, str = tt >> 6, r = tt & 63;
        const uint4* src = (const uint4*)((str ? g_B1l : g_B1h) + r * 104);
        uint4* dst = (uint4*)((str ? sBl : sBh) + r * 104);
#pragma unroll
        for (int q = 0; q < 13; ++q) dst[q] = src[q];
    }
    if (tid < 64) bs[tid] = b1[tid];

    // produce A: each thread 3 cols of its row
    int edge = blockIdx.x * 128 + row;
    int n = edge / KNN;
    int pj = g_nbr[edge];
    float e[6];
    {
        const float* Pi = pos + n * 3;
        const float* Pj = pos + pj * 3;
        e[0] = Pi[0]; e[1] = Pi[1]; e[2] = Pi[2];
        e[3] = Pj[0] - Pi[0]; e[4] = Pj[1] - Pi[1]; e[5] = Pj[2] - Pi[2];
    }
#pragma unroll
    for (int cc = 0; cc < 3; ++cc) {
        int cl = cg * 3 + cc;
        int i = cl % 3;
        float ham = (i == 1) ? 1.0f : 0.08f;   // hamming, W=3
        float a = e[cl] * ham;
        float s, c; __sincosf(a, &s, &c);
        uint32_t* ph = (uint32_t*)&sAh[row * SA1 + cl * 16];
        uint32_t* pl = (uint32_t*)&sAl[row * SA1 + cl * 16];
        float ck = c, sk = s;
#pragma unroll
        for (int k = 0; k < 5; ++k) {
            if (k) { float cn = ck * c - sk * s, sn = sk * c + ck * s; ck = cn; sk = sn; }
            __half chh = __float2half_rn(ck), shh = __float2half_rn(sk);
            ph[k] = pack_h2(ck, sk);
            pl[k] = pack_h2(ck - __half2float(chh), sk - __half2float(shh));
        }
        ph[5] = ph[6] = ph[7] = 0u;
        pl[5] = pl[6] = pl[7] = 0u;
    }
    __syncthreads();

    float acc[2][4][4];
#pragma unroll
    for (int m = 0; m < 2; ++m)
#pragma unroll
        for (int nf = 0; nf < 4; ++nf)
#pragma unroll
            for (int q = 0; q < 4; ++q) acc[m][nf][q] = 0.f;

#pragma unroll
    for (int ks = 0; ks < 6; ++ks) {
        int kb = ks * 16;
        uint32_t ah[2][4], al[2][4];
#pragma unroll
        for (int m = 0; m < 2; ++m) {
            int rb = (wm * 32 + m * 16 + qr) * SA1 + kb + qk * 2;
            ah[m][0] = *(const uint32_t*)&sAh[rb];
            ah[m][1] = *(const uint32_t*)&sAh[rb + 8 * SA1];
            ah[m][2] = *(const uint32_t*)&sAh[rb + 8];
            ah[m][3] = *(const uint32_t*)&sAh[rb + 8 * SA1 + 8];
            al[m][0] = *(const uint32_t*)&sAl[rb];
            al[m][1] = *(const uint32_t*)&sAl[rb + 8 * SA1];
            al[m][2] = *(const uint32_t*)&sAl[rb + 8];
            al[m][3] = *(const uint32_t*)&sAl[rb + 8 * SA1 + 8];
        }
#pragma unroll
        for (int nf = 0; nf < 4; ++nf) {
            int bb = (wn * 32 + nf * 8 + qr) * SA1 + kb + qk * 2;
            uint32_t bh0 = *(const uint32_t*)&sBh[bb];
            uint32_t bh1 = *(const uint32_t*)&sBh[bb + 8];
            uint32_t bl0 = *(const uint32_t*)&sBl[bb];
            uint32_t bl1 = *(const uint32_t*)&sBl[bb + 8];
#pragma unroll
            for (int m = 0; m < 2; ++m) {
                mma_f16(acc[m][nf], ah[m][0], ah[m][1], ah[m][2], ah[m][3], bh0, bh1);
                mma_f16(acc[m][nf], al[m][0], al[m][1], al[m][2], al[m][3], bh0, bh1);
                mma_f16(acc[m][nf], ah[m][0], ah[m][1], ah[m][2], ah[m][3], bl0, bl1);
            }
        }
    }
    __syncthreads();   // done reading A/B smem; reuse as transpose buffer

#pragma unroll
    for (int m = 0; m < 2; ++m) {
        int r0 = wm * 32 + m * 16 + qr;
#pragma unroll
        for (int nf = 0; nf < 4; ++nf) {
            int c0 = wn * 32 + nf * 8 + qk * 2;
            tr[c0 * 132 + r0]           = acc[m][nf][0];
            tr[(c0 + 1) * 132 + r0]     = acc[m][nf][1];
            tr[c0 * 132 + r0 + 8]       = acc[m][nf][2];
            tr[(c0 + 1) * 132 + r0 + 8] = acc[m][nf][3];
        }
    }
    __syncthreads();
    int e0 = blockIdx.x * 128;
    for (int idx = tid; idx < 64 * 128; idx += 256) {
        int o = idx >> 7, r = idx & 127;
        g_h1T[(size_t)o * NEDGE + e0 + r] = tr[o * 132 + r] + bs[o];
    }
}

// ---------------- layer3 basis materialization (one pass) -------------------
__global__ void basis3_kernel() {
    int mt = blockIdx.x, ch = blockIdx.y;
    int t = threadIdx.x, row = t & 127, cg = t >> 7;
    size_t base = ((size_t)(mt * 28 + ch) * 128 + row) * 40;  // uint32 units
    uint32_t* dh = (uint32_t*)g_Phi3h + base;
    uint32_t* dl = (uint32_t*)g_Phi3l + base;
#pragma unroll
    for (int cc = 0; cc < 4; ++cc) {
        int cl = cg * 4 + cc;
        int col = ch * 8 + cl;
        int w = col / 32, i = col - w * 32;
        float ham = 0.54f - 0.46f * cosf(6.2831853071795864f * (float)i / 31.0f);
        float a = g_x1T[(size_t)(w * 16 + i) * NPTS + mt * 128 + row] * ham;
        float s, c; __sincosf(a, &s, &c);
        float ck = c, sk = s;
#pragma unroll
        for (int k = 0; k < 5; ++k) {
            if (k) { float cn = ck * c - sk * s, sn = sk * c + ck * s; ck = cn; sk = sn; }
            __half chh = __float2half_rn(ck), shh = __float2half_rn(sk);
            dh[cl * 5 + k] = pack_h2(ck, sk);
            dl[cl * 5 + k] = pack_h2(ck - __half2float(chh), sk - __half2float(shh));
        }
    }
}

// ---------------- fp16x2 pipelined fused-basis GEMM (layers 2,3) ------------
// LAYER==2: basis produced in-kernel (pipelined sincos), B double-buffered cp.async.
// LAYER==3: A (Phi3 hi/lo) + B all cp.async double-buffered from global.
template<int LAYER>
__global__ void __launch_bounds__(256, (LAYER == 2) ? 2 : 1)
kan_mma(const float* __restrict__ bias) {
    constexpr int W    = (LAYER == 2) ? 16 : 32;
    constexpr int S    = (LAYER == 2) ? 8  : 16;
    constexpr int DOUT = (LAYER == 2) ? 128 : 1024;
    constexpr int M    = (LAYER == 2) ? NEDGE : NPTS;
    constexpr int NCH  = (LAYER == 2) ? 14 : 28;
    constexpr int KTOT = (LAYER == 2) ? 1120 : 2240;
    constexpr int SA   = 88;
    constexpr uint32_t RB = 128 * SA * 2;   // 22528 B per region

    extern __shared__ unsigned char smem[];
    uint32_t smem_b = (uint32_t)__cvta_generic_to_shared(smem);

    const float* x = (LAYER == 2) ? g_h1T : g_x1T;
    const __half* Bg = (LAYER == 2) ? g_B2 : g_B3;
    float* y = (LAYER == 2) ? g_y2 : g_x3;

    int m0 = blockIdx.x * 128;
    int n0 = blockIdx.y * 128;
    int tid = threadIdx.x;
    int lane = tid & 31, warp = tid >> 5;
    int wm = warp & 3, wn = warp >> 2;
    int qr = lane >> 2, qk = lane & 3;
    int row = tid & 127, cg = tid >> 7;

    float acc[2][8][4];
#pragma unroll
    for (int m = 0; m < 2; ++m)
#pragma unroll
        for (int nn = 0; nn < 8; ++nn)
#pragma unroll
            for (int q = 0; q < 4; ++q) acc[m][nn][q] = 0.f;

    float cv[4], sv[4];

    // sincos for chunk ch into regs (layer2 only)
    auto gen = [&](int ch) {
#pragma unroll
        for (int cc = 0; cc < 4; ++cc) {
            int cl = cg * 4 + cc, col = ch * 8 + cl;
            int w = col / W, i = col - w * W;
            float ham = 0.54f - 0.46f * cosf(6.2831853071795864f * (float)i / (float)(W - 1));
            float a = x[(size_t)(w * S + i) * M + m0 + row] * ham;
            __sincosf(a, &sv[cc], &cv[cc]);
        }
    };
    // Chebyshev expand + pack + STS (layer2 only; A single-buffered)
    auto storeA = [&]() {
        __half* sAh = (__half*)smem;
        __half* sAl = (__half*)(smem + RB);
#pragma unroll
        for (int cc = 0; cc < 4; ++cc) {
            int cl = cg * 4 + cc;
            float c = cv[cc], s = sv[cc], ck = c, sk = s;
            uint32_t* ph = (uint32_t*)&sAh[row * SA + cl * 10];
            uint32_t* pl = (uint32_t*)&sAl[row * SA + cl * 10];
#pragma unroll
            for (int k = 0; k < 5; ++k) {
                if (k) { float cn = ck * c - sk * s, sn = sk * c + ck * s; ck = cn; sk = sn; }
                __half chh = __float2half_rn(ck), shh = __float2half_rn(sk);
                ph[k] = pack_h2(ck, sk);
                pl[k] = pack_h2(ck - __half2float(chh), sk - __half2float(shh));
            }
        }
    };
    // B cp.async for chunk ch into buffer b (layer2)
    auto bload = [&](int ch, int b) {
        if (tid < 128) {
            const __half* src = Bg + (size_t)(n0 + tid) * KTOT + ch * 80;
            uint32_t dst = smem_b + 2 * RB + (uint32_t)b * RB + (uint32_t)tid * 176;
#pragma unroll
            for (int q = 0; q < 10; ++q) cp16(dst + q * 16, src + q * 8);
        }
        CP_COMMIT();
    };
    // A(hi/lo) + B cp.async for chunk ch into buffer b (layer3)
    auto load3 = [&](int ch, int b) {
        size_t ablk = (size_t)(blockIdx.x * 28 + ch) * 128 * 80;
        for (int j = tid; j < 384; j += 256) {
            int reg = j >> 7, r = j & 127;
            const __half* src;
            uint32_t dst;
            if (reg == 0)      { src = g_Phi3h + ablk + r * 80; dst = smem_b + (uint32_t)b * RB + (uint32_t)r * 176; }
            else if (reg == 1) { src = g_Phi3l + ablk + r * 80; dst = smem_b + 2 * RB + (uint32_t)b * RB + (uint32_t)r * 176; }
            else               { src = Bg + (size_t)(n0 + r) * KTOT + ch * 80; dst = smem_b + 4 * RB + (uint32_t)b * RB + (uint32_t)r * 176; }
#pragma unroll
            for (int q = 0; q < 10; ++q) cp16(dst + q * 16, src + q * 8);
        }
        CP_COMMIT();
    };
    // MMA over one 80-k chunk (2 streams)
    auto mma_phase = [&](const __half* sAh, const __half* sAl, const __half* sB) {
#pragma unroll
        for (int ks = 0; ks < 5; ++ks) {
            int kb = ks * 16;
            uint32_t ah[2][4], al[2][4];
#pragma unroll
            for (int m = 0; m < 2; ++m) {
                int rb = (wm * 32 + m * 16 + qr) * SA + kb + qk * 2;
                ah[m][0] = *(const uint32_t*)&sAh[rb];
                ah[m][1] = *(const uint32_t*)&sAh[rb + 8 * SA];
                ah[m][2] = *(const uint32_t*)&sAh[rb + 8];
                ah[m][3] = *(const uint32_t*)&sAh[rb + 8 * SA + 8];
                al[m][0] = *(const uint32_t*)&sAl[rb];
                al[m][1] = *(const uint32_t*)&sAl[rb + 8 * SA];
                al[m][2] = *(const uint32_t*)&sAl[rb + 8];
                al[m][3] = *(const uint32_t*)&sAl[rb + 8 * SA + 8];
            }
#pragma unroll
            for (int nn = 0; nn < 8; ++nn) {
                int bb = (wn * 64 + nn * 8 + qr) * SA + kb + qk * 2;
                uint32_t bh0 = *(const uint32_t*)&sB[bb];
                uint32_t bh1 = *(const uint32_t*)&sB[bb + 8];
#pragma unroll
                for (int m = 0; m < 2; ++m) {
                    mma_f16(acc[m][nn], ah[m][0], ah[m][1], ah[m][2], ah[m][3], bh0, bh1);
                    mma_f16(acc[m][nn], al[m][0], al[m][1], al[m][2], al[m][3], bh0, bh1);
                }
            }
        }
    };

    if constexpr (LAYER == 2) {
        gen(0);
        bload(0, 0);
        storeA();
        CP_WAIT0();
        __syncthreads();
        for (int ch = 0; ch < NCH; ++ch) {
            int nxt = ch + 1;
            if (nxt < NCH) { bload(nxt, nxt & 1); gen(nxt); }   // overlaps MMA below
            mma_phase((const __half*)smem, (const __half*)(smem + RB),
                      (const __half*)(smem + 2 * RB + (uint32_t)(ch & 1) * RB));
            __syncthreads();
            if (nxt < NCH) storeA();
            CP_WAIT0();
            __syncthreads();
        }
    } else {
        load3(0, 0);
        CP_WAIT0();
        __syncthreads();
        for (int ch = 0; ch < NCH; ++ch) {
            int nxt = ch + 1;
            if (nxt < NCH) load3(nxt, nxt & 1);                 // overlaps MMA below
            uint32_t b = ch & 1;
            mma_phase((const __half*)(smem + b * RB),
                      (const __half*)(smem + 2 * RB + b * RB),
                      (const __half*)(smem + 4 * RB + b * RB));
            __syncthreads();
            CP_WAIT0();
            __syncthreads();
        }
    }

    // epilogue
#pragma unroll
    for (int m = 0; m < 2; ++m) {
        int r0 = m0 + wm * 32 + m * 16 + qr;
#pragma unroll
        for (int nn = 0; nn < 8; ++nn) {
            int c0 = n0 + wn * 64 + nn * 8 + qk * 2;
            float bv0 = bias[c0], bv1 = bias[c0 + 1];
            float2 v0 = make_float2(acc[m][nn][0] + bv0, acc[m][nn][1] + bv1);
            float2 v1 = make_float2(acc[m][nn][2] + bv0, acc[m][nn][3] + bv1);
            *(float2*)&y[(size_t)r0 * DOUT + c0] = v0;
            *(float2*)&y[(size_t)(r0 + 8) * DOUT + c0] = v1;
        }
    }
}

// ---------------- max over K neighbors, transposed output -------------------
__global__ void maxagg_kernel() {
    extern __shared__ unsigned char dynsm[];
    float* s = (float*)dynsm;               // [128][133]
    int n0 = blockIdx.x * 128;
    for (int idx = threadIdx.x; idx < 128 * 128; idx += 256) {
        int p = idx >> 7, c = idx & 127;
        const float* src = g_y2 + ((size_t)(n0 + p) * KNN) * 128 + c;
        float m = src[0];
#pragma unroll
        for (int j = 1; j < KNN; ++j) m = fmaxf(m, src[j * 128]);
        s[c * 133 + p] = m;
    }
    __syncthreads();
    for (int idx = threadIdx.x; idx < 128 * 128; idx += 256) {
        int c = idx >> 7, p = idx & 127;
        g_x1T[(size_t)c * NPTS + n0 + p] = s[c * 133 + p];
    }
}

// ---------------- segment max + mean pooling ----------------
__global__ void pool_kernel() {
    int b = blockIdx.x;
    int c = blockIdx.y * 128 + threadIdx.x;
    const float* p = g_x3 + (size_t)b * PPC * 1024 + c;
    float mx = -1e30f, sm = 0.f;
    for (int pt = 0; pt < PPC; ++pt) {
        float v = p[(size_t)pt * 1024];
        mx = fmaxf(mx, v); sm += v;
    }
    g_xg[b * 2048 + c] = mx;
    g_xg[b * 2048 + 1024 + c] = sm * (1.0f / 1024.0f);
}

// ---------------- layer4 ----------------
__global__ void layer4_part() {
    __shared__ float xs[2048];
    __shared__ float wsum[8][40];
    int b = blockIdx.x, sl = blockIdx.y, tid = threadIdx.x;
    for (int i = tid; i < 2048; i += 256) xs[i] = g_xg[b * 2048 + i];
    __syncthreads();
    float acc[40];
#pragma unroll
    for (int o = 0; o < 40; ++o) acc[o] = 0.f;
    for (int pp = tid; pp < 480; pp += 256) {
        int p = sl * 480 + pp;
        int w = p >> 8, i = p & 255;
        int d = (w << 7) + i;
        float ham = 0.54f - 0.46f * cosf(6.2831853071795864f * (float)i / 255.0f);
        float a = xs[d] * ham;
        float s, c; __sincosf(a, &s, &c);
        float ck = c, sk = s;
        const float* bp = g_Bp4 + p * 400;
#pragma unroll
        for (int k = 0; k < 5; ++k) {
            if (k > 0) { float cn = ck * c - sk * s, sn = sk * c + ck * s; ck = cn; sk = sn; }
            const float* c0 = bp + (2 * k) * 40;
            const float* s0 = bp + (2 * k + 1) * 40;
#pragma unroll
            for (int o = 0; o < 40; ++o) acc[o] += ck * c0[o] + sk * s0[o];
        }
    }
    int lane = tid & 31, wp = tid >> 5;
#pragma unroll
    for (int o = 0; o < 40; ++o) {
        float t = acc[o];
#pragma unroll
        for (int off = 16; off > 0; off >>= 1) t += __shfl_down_sync(0xffffffffu, t, off);
        if (lane == 0) wsum[wp][o] = t;
    }
    __syncthreads();
    if (tid < 40) {
        float t = 0.f;
#pragma unroll
        for (int w8 = 0; w8 < 8; ++w8) t += wsum[w8][tid];
        g_l4p[(b * 8 + sl) * 40 + tid] = t;
    }
}

__global__ void layer4_final(const float* __restrict__ b4, float* __restrict__ out) {
    int t = threadIdx.x;
    if (t < 320) {
        int o = t % 40;
        int b = t / 40;
        float s = b4[o];
#pragma unroll
        for (int sl = 0; sl < 8; ++sl) s += g_l4p[(b * 8 + sl) * 40 + o];
        out[t] = s;
    }
}

// ---------------- launch ----------------
extern "C" void kernel_launch(void* const* d_in, const int* in_sizes, int n_in,
                              void* d_out, int out_size) {
    (void)in_sizes; (void)n_in; (void)out_size;
    const float* pos = (const float*)d_in[0];
    const float* c1  = (const float*)d_in[2];
    const float* b1  = (const float*)d_in[3];
    const float* c2  = (const float*)d_in[4];
    const float* b2  = (const float*)d_in[5];
    const float* c3  = (const float*)d_in[6];
    const float* b3  = (const float*)d_in[7];
    const float* c4  = (const float*)d_in[8];
    const float* b4  = (const float*)d_in[9];
    float* out = (float*)d_out;

    const int SM_L1  = 80128;                 // layer1_mma
    const int SM_K2  = 4 * 22528;             // 90112  (A hi/lo + B x2)
    const int SM_K3  = 6 * 22528;             // 135168 (A hi/lo x2 + B x2)
    const int SM_MAX = 128 * 133 * 4;         // 68096
    cudaFuncSetAttribute(layer1_mma, cudaFuncAttributeMaxDynamicSharedMemorySize, SM_L1);
    cudaFuncSetAttribute(kan_mma<2>, cudaFuncAttributeMaxDynamicSharedMemorySize, SM_K2);
    cudaFuncSetAttribute(kan_mma<3>, cudaFuncAttributeMaxDynamicSharedMemorySize, SM_K3);
    cudaFuncSetAttribute(maxagg_kernel, cudaFuncAttributeMaxDynamicSharedMemorySize, SM_MAX);

    knn_kernel<<<32, 256>>>(pos);                                   // 0
    pack12<<<587, 256>>>(c1, c2);                                   // 1
    layer1_mma<<<NEDGE / 128, 256, SM_L1>>>(pos, b1);               // 2
    kan_mma<2><<<dim3(NEDGE / 128, 1), 256, SM_K2>>>(b2);           // 3  <- ncu slot
    maxagg_kernel<<<NPTS / 128, 256, SM_MAX>>>();                   // 4
    pack3<<<8960, 256>>>(c3);                                       // 5
    basis3_kernel<<<dim3(64, 28), 256>>>();                         // 6
    kan_mma<3><<<dim3(NPTS / 128, 8), 256, SM_K3>>>(b3);            // 7
    pack_coef4<<<6000, 256>>>(c4);                                  // 8
    pool_kernel<<<dim3(NB, 8), 128>>>();                            // 9
    layer4_part<<<dim3(NB, 8), 256>>>();                            // 10
    layer4_final<<<1, 320>>>(b4, out);                              // 11
}

// round 12
// speedup vs baseline: 1.1552x; 1.1552x over previous
#include <cuda_runtime.h>
#include <cuda_fp16.h>
#include <cstdint>

#define NB    8
#define PPC   1024
#define NPTS  8192
#define KNN   20
#define NEDGE (NPTS*KNN)

// ---------------- scratch (device globals; allocation-free) ----------------
__device__ int   g_nbr[NEDGE];
__device__ __align__(16) float g_h1T[64*NEDGE];    // layer1 out, TRANSPOSED [c][edge]
__device__ __align__(16) float g_y2[NEDGE*128];    // layer2 out (pre-max), row-major
__device__ __align__(16) float g_x1T[128*NPTS];    // after max over K, TRANSPOSED [c][n]
__device__ __align__(16) float g_x3[NPTS*1024];    // layer3 out, row-major
__device__ float g_xg[NB*2048];                    // pooled [max | mean]
__device__ __align__(16) float g_Bp4[38400*40];    // layer4 coeffs [f][o]
__device__ __align__(16) __half g_B1h[64*104];     // layer1 coeffs [o][96k pad104] hi
__device__ __align__(16) __half g_B1l[64*104];     // lo
__device__ __align__(16) __half g_B2[128*1120];    // layer2 coeffs [o][f] fp16
__device__ __align__(16) __half g_B3[1024*2240];   // layer3 coeffs [o][f] fp16
__device__ float g_l4p[NB*8*40];

// ---------------- small helpers ----------------
__device__ __forceinline__ uint32_t pack_h2(float lo, float hi) {
    __half2 h = __floats2half2_rn(lo, hi);
    return *(uint32_t*)&h;
}
__device__ __forceinline__ void mma_f16(float* c, const uint32_t* a,
                                        uint32_t b0, uint32_t b1) {
    asm volatile(
        "mma.sync.aligned.m16n8k16.row.col.f32.f16.f16.f32 "
        "{%0,%1,%2,%3}, {%4,%5,%6,%7}, {%8,%9}, {%0,%1,%2,%3};\n"
        : "+f"(c[0]), "+f"(c[1]), "+f"(c[2]), "+f"(c[3])
        : "r"(a[0]), "r"(a[1]), "r"(a[2]), "r"(a[3]), "r"(b0), "r"(b1));
}
__device__ __forceinline__ void ldsm4(uint32_t* r, uint32_t addr) {
    asm volatile("ldmatrix.sync.aligned.m8n8.x4.shared.b16 {%0,%1,%2,%3}, [%4];"
                 : "=r"(r[0]), "=r"(r[1]), "=r"(r[2]), "=r"(r[3]) : "r"(addr));
}

// ---------------- packing kernels ----------------
// pack12: layer1 B (hi/lo, padded [64][104]) + layer2 B (fp16 [o][f])
__global__ void pack12(const float* __restrict__ c1, const float* __restrict__ c2) {
    int idx = blockIdx.x * 256 + threadIdx.x;
    if (idx < 64 * 104) {
        int o = idx / 104, jj = idx - o * 104;
        float v = 0.f;
        if (jj < 96) {
            int c = jj >> 4, j = jj & 15;
            if (j < 10) {
                int trig = j & 1, k = j >> 1, w = c / 3, i = c % 3;
                v = c1[(((trig * 64 + o) * 2 + w) * 3 + i) * 5 + k];
            }
        }
        __half h = __float2half_rn(v);
        g_B1h[idx] = h;
        g_B1l[idx] = __float2half_rn(v - __half2float(h));
    } else {
        int id2 = idx - 64 * 104;
        if (id2 < 128 * 1120) {
            int o = id2 / 1120, f = id2 - o * 1120;
            int trig = f & 1, f2 = f >> 1, k = f2 % 5, wi = f2 / 5, w = wi / 16, i = wi - w * 16;
            g_B2[id2] = __float2half_rn(
                c2[((((size_t)trig * 128 + o) * 7 + w) * 16 + i) * 5 + k]);
        }
    }
}

__global__ void pack3(const float* __restrict__ c3) {
    int idx = blockIdx.x * 256 + threadIdx.x;
    if (idx >= 1024 * 2240) return;
    int o = idx / 2240, f = idx - o * 2240;
    int trig = f & 1, f2 = f >> 1, k = f2 % 5, wi = f2 / 5, w = wi / 32, i = wi - w * 32;
    g_B3[idx] = __float2half_rn(
        c3[((((size_t)trig * 1024 + o) * 7 + w) * 32 + i) * 5 + k]);
}

__global__ void pack_coef4(const float* __restrict__ src) {
    const int dout = 40, nw = 15, W = 256, g = 5;
    int idx = blockIdx.x * 256 + threadIdx.x;
    if (idx >= 38400 * 40) return;
    int o = idx % dout;
    int f = idx / dout;
    int trig = f & 1;
    int f2 = f >> 1;
    int k = f2 % g;
    int wi = f2 / g;
    int w = wi / W;
    int i = wi - w * W;
    g_Bp4[idx] = src[((((size_t)trig * dout + o) * nw + w) * W + i) * g + k];
}

// ---------------- kNN: register top-20 per query thread ----------------
__global__ void knn_kernel(const float* __restrict__ pos) {
    __shared__ float sx[PPC], sy[PPC], sz[PPC];
    int tid = threadIdx.x;
    int b   = blockIdx.x >> 2;
    int ql  = ((blockIdx.x & 3) << 8) + tid;
    for (int p = tid; p < PPC; p += 256) {
        const float* pp = pos + (b * PPC + p) * 3;
        sx[p] = pp[0]; sy[p] = pp[1]; sz[p] = pp[2];
    }
    __syncthreads();
    float qx = sx[ql], qy = sy[ql], qz = sz[ql];
    float v[KNN]; int id[KNN];
#pragma unroll
    for (int j = 0; j < KNN; ++j) { v[j] = 1e30f; id[j] = -1; }
    float vmax = 1e30f; int mpos = 0;
    for (int p = 0; p < PPC; ++p) {
        float dx = sx[p] - qx, dy = sy[p] - qy, dz = sz[p] - qz;
        float d = dx * dx + dy * dy + dz * dz;
        if (p == ql) d = 1e30f;
        if (d < vmax) {
#pragma unroll
            for (int j = 0; j < KNN; ++j) if (j == mpos) { v[j] = d; id[j] = p; }
            vmax = v[0]; mpos = 0;
#pragma unroll
            for (int j = 1; j < KNN; ++j) if (v[j] > vmax) { vmax = v[j]; mpos = j; }
        }
    }
    int q = b * PPC + ql;
#pragma unroll
    for (int j = 0; j < KNN; ++j) g_nbr[q * KNN + j] = b * PPC + id[j];
}

// ---------------- layer1 as fused-basis HMMA (fp16x3), M=128/block -----------
__global__ void __launch_bounds__(256, 2)
layer1_mma(const float* __restrict__ pos, const float* __restrict__ b1) {
    constexpr int SA1 = 104;
    extern __shared__ unsigned char smem[];
    __half* sAh = (__half*)smem;                     // 26624 B
    __half* sAl = (__half*)(smem + 26624);           // 26624 B
    __half* sBh = (__half*)(smem + 53248);           // 13312 B
    __half* sBl = (__half*)(smem + 66560);           // 13312 B
    float*  bs  = (float*)(smem + 79872);            // 256 B
    float*  tr  = (float*)smem;                      // reuse after MMA

    int tid = threadIdx.x, lane = tid & 31, warp = tid >> 5;
    int wm = warp & 3, wn = warp >> 2;
    int qr = lane >> 2, qk = lane & 3;
    int row = tid & 127, cg = tid >> 7;

    if (tid >= 128) {
        int tt = tid - 128, str = tt >> 6, r = tt & 63;
        const uint4* src = (const uint4*)((str ? g_B1l : g_B1h) + r * 104);
        uint4* dst = (uint4*)((str ? sBl : sBh) + r * 104);
#pragma unroll
        for (int q = 0; q < 13; ++q) dst[q] = src[q];
    }
    if (tid < 64) bs[tid] = b1[tid];

    int edge = blockIdx.x * 128 + row;
    int n = edge / KNN;
    int pj = g_nbr[edge];
    float e[6];
    {
        const float* Pi = pos + n * 3;
        const float* Pj = pos + pj * 3;
        e[0] = Pi[0]; e[1] = Pi[1]; e[2] = Pi[2];
        e[3] = Pj[0] - Pi[0]; e[4] = Pj[1] - Pi[1]; e[5] = Pj[2] - Pi[2];
    }
#pragma unroll
    for (int cc = 0; cc < 3; ++cc) {
        int cl = cg * 3 + cc;
        int i = cl % 3;
        float ham = (i == 1) ? 1.0f : 0.08f;   // hamming, W=3
        float a = e[cl] * ham;
        float s, c; __sincosf(a, &s, &c);
        uint32_t* ph = (uint32_t*)&sAh[row * SA1 + cl * 16];
        uint32_t* pl = (uint32_t*)&sAl[row * SA1 + cl * 16];
        float ck = c, sk = s;
#pragma unroll
        for (int k = 0; k < 5; ++k) {
            if (k) { float cn = ck * c - sk * s, sn = sk * c + ck * s; ck = cn; sk = sn; }
            __half chh = __float2half_rn(ck), shh = __float2half_rn(sk);
            ph[k] = pack_h2(ck, sk);
            pl[k] = pack_h2(ck - __half2float(chh), sk - __half2float(shh));
        }
        ph[5] = ph[6] = ph[7] = 0u;
        pl[5] = pl[6] = pl[7] = 0u;
    }
    __syncthreads();

    float acc[2][4][4];
#pragma unroll
    for (int m = 0; m < 2; ++m)
#pragma unroll
        for (int nf = 0; nf < 4; ++nf)
#pragma unroll
            for (int q = 0; q < 4; ++q) acc[m][nf][q] = 0.f;

#pragma unroll
    for (int ks = 0; ks < 6; ++ks) {
        int kb = ks * 16;
        uint32_t ah[2][4], al[2][4];
#pragma unroll
        for (int m = 0; m < 2; ++m) {
            int rb = (wm * 32 + m * 16 + qr) * SA1 + kb + qk * 2;
            ah[m][0] = *(const uint32_t*)&sAh[rb];
            ah[m][1] = *(const uint32_t*)&sAh[rb + 8 * SA1];
            ah[m][2] = *(const uint32_t*)&sAh[rb + 8];
            ah[m][3] = *(const uint32_t*)&sAh[rb + 8 * SA1 + 8];
            al[m][0] = *(const uint32_t*)&sAl[rb];
            al[m][1] = *(const uint32_t*)&sAl[rb + 8 * SA1];
            al[m][2] = *(const uint32_t*)&sAl[rb + 8];
            al[m][3] = *(const uint32_t*)&sAl[rb + 8 * SA1 + 8];
        }
#pragma unroll
        for (int nf = 0; nf < 4; ++nf) {
            int bb = (wn * 32 + nf * 8 + qr) * SA1 + kb + qk * 2;
            uint32_t bh0 = *(const uint32_t*)&sBh[bb];
            uint32_t bh1 = *(const uint32_t*)&sBh[bb + 8];
            uint32_t bl0 = *(const uint32_t*)&sBl[bb];
            uint32_t bl1 = *(const uint32_t*)&sBl[bb + 8];
#pragma unroll
            for (int m = 0; m < 2; ++m) {
                mma_f16(acc[m][nf], ah[m], bh0, bh1);
                mma_f16(acc[m][nf], al[m], bh0, bh1);
                mma_f16(acc[m][nf], ah[m], bl0, bl1);
            }
        }
    }
    __syncthreads();   // done reading A/B smem; reuse as transpose buffer

#pragma unroll
    for (int m = 0; m < 2; ++m) {
        int r0 = wm * 32 + m * 16 + qr;
#pragma unroll
        for (int nf = 0; nf < 4; ++nf) {
            int c0 = wn * 32 + nf * 8 + qk * 2;
            tr[c0 * 132 + r0]           = acc[m][nf][0];
            tr[(c0 + 1) * 132 + r0]     = acc[m][nf][1];
            tr[c0 * 132 + r0 + 8]       = acc[m][nf][2];
            tr[(c0 + 1) * 132 + r0 + 8] = acc[m][nf][3];
        }
    }
    __syncthreads();
    int e0 = blockIdx.x * 128;
    for (int idx = tid; idx < 64 * 128; idx += 256) {
        int o = idx >> 7, r = idx & 127;
        g_h1T[(size_t)o * NEDGE + e0 + r] = tr[o * 132 + r] + bs[o];
    }
}

// ---------------- fp16x2 fused-basis GEMM, ldmatrix operand path ------------
template<int LAYER>
__global__ void __launch_bounds__(256, 2)
kan_mma(const float* __restrict__ bias) {
    constexpr int W    = (LAYER == 2) ? 16 : 32;
    constexpr int S    = (LAYER == 2) ? 8  : 16;
    constexpr int DOUT = (LAYER == 2) ? 128 : 1024;
    constexpr int M    = (LAYER == 2) ? NEDGE : NPTS;
    constexpr int NCH  = (LAYER == 2) ? 14 : 28;
    constexpr int KTOT = (LAYER == 2) ? 1120 : 2240;
    constexpr int SA   = 88;             // padded k-stride (fp16 units)

    extern __shared__ unsigned char dynsm[];
    __half* sAh = (__half*)dynsm;
    __half* sAl = sAh + 128 * SA;
    __half* sBh = sAl + 128 * SA;
    uint32_t sAh_u = (uint32_t)__cvta_generic_to_shared(sAh);
    uint32_t sAl_u = (uint32_t)__cvta_generic_to_shared(sAl);
    uint32_t sBh_u = (uint32_t)__cvta_generic_to_shared(sBh);

    const float* x = (LAYER == 2) ? g_h1T : g_x1T;     // [d][M]
    const __half* Bg = (LAYER == 2) ? g_B2 : g_B3;
    float* y = (LAYER == 2) ? g_y2 : g_x3;

    int m0 = blockIdx.x * 128;
    int n0 = blockIdx.y * 128;
    int tid = threadIdx.x;
    int lane = tid & 31, warp = tid >> 5;
    int wm = warp & 3, wn = warp >> 2;   // warp tile: 32 rows x 64 cols
    int qr = lane >> 2, qk = lane & 3;
    int row = tid & 127, cg = tid >> 7;  // producer mapping

    // ldmatrix per-lane offsets (element units)
    int a_row_off = (lane & 7) + ((lane >> 3) & 1) * 8;
    int a_col_off = (lane >> 4) * 8;
    int b_row_off = (lane & 7) + ((lane >> 4) & 1) * 8;
    int b_col_off = ((lane >> 3) & 1) * 8;

    float acc[2][8][4];
#pragma unroll
    for (int m = 0; m < 2; ++m)
#pragma unroll
        for (int nn = 0; nn < 8; ++nn)
#pragma unroll
            for (int q = 0; q < 4; ++q) acc[m][nn][q] = 0.f;

    for (int ch = 0; ch < NCH; ++ch) {
        __syncthreads();
        // ---- produce A: all 256 threads, 4 cols each (128 rows x 8 cols) ----
#pragma unroll
        for (int cc = 0; cc < 4; ++cc) {
            int cl = cg * 4 + cc;            // col 0..7 within chunk
            int col = ch * 8 + cl;
            int w = col / W, i = col - w * W;
            float ham = 0.54f - 0.46f * cosf(6.2831853071795864f * (float)i / (float)(W - 1));
            float a = x[(size_t)(w * S + i) * M + m0 + row] * ham;
            float s, c; __sincosf(a, &s, &c);
            float ck = c, sk = s;
            uint32_t* ph = (uint32_t*)&sAh[row * SA + cl * 10];
            uint32_t* pl = (uint32_t*)&sAl[row * SA + cl * 10];
#pragma unroll
            for (int k = 0; k < 5; ++k) {
                if (k > 0) { float cn = ck * c - sk * s, sn = sk * c + ck * s; ck = cn; sk = sn; }
                __half chh = __float2half_rn(ck);
                __half shh = __float2half_rn(sk);
                ph[k] = pack_h2(ck, sk);
                pl[k] = pack_h2(ck - __half2float(chh), sk - __half2float(shh));
            }
        }
        // ---- stage B: threads 0-127, one n-row each (80 fp16 = 10 uint4) ----
        if (tid < 128) {
            const uint4* gb = (const uint4*)(Bg + (size_t)(n0 + tid) * KTOT + ch * 80);
            uint4* sp = (uint4*)(sBh + tid * SA);
#pragma unroll
            for (int q = 0; q < 10; ++q) sp[q] = gb[q];
        }
        __syncthreads();

#pragma unroll
        for (int ks = 0; ks < 5; ++ks) {
            int kb = ks * 16;
            uint32_t ah[2][4], al[2][4];
#pragma unroll
            for (int m = 0; m < 2; ++m) {
                uint32_t abase =
                    (uint32_t)(((wm * 32 + m * 16 + a_row_off) * SA + kb + a_col_off) * 2);
                ldsm4(ah[m], sAh_u + abase);
                ldsm4(al[m], sAl_u + abase);
            }
#pragma unroll
            for (int nn = 0; nn < 8; nn += 2) {
                uint32_t b[4];
                uint32_t bbase =
                    (uint32_t)(((wn * 64 + nn * 8 + b_row_off) * SA + kb + b_col_off) * 2);
                ldsm4(b, sBh_u + bbase);
#pragma unroll
                for (int m = 0; m < 2; ++m) {
                    mma_f16(acc[m][nn],     ah[m], b[0], b[1]);
                    mma_f16(acc[m][nn],     al[m], b[0], b[1]);
                    mma_f16(acc[m][nn + 1], ah[m], b[2], b[3]);
                    mma_f16(acc[m][nn + 1], al[m], b[2], b[3]);
                }
            }
        }
    }

    // epilogue
#pragma unroll
    for (int m = 0; m < 2; ++m) {
        int r0 = m0 + wm * 32 + m * 16 + qr;
#pragma unroll
        for (int nn = 0; nn < 8; ++nn) {
            int c0 = n0 + wn * 64 + nn * 8 + qk * 2;
            float bv0 = bias[c0], bv1 = bias[c0 + 1];
            float2 v0 = make_float2(acc[m][nn][0] + bv0, acc[m][nn][1] + bv1);
            float2 v1 = make_float2(acc[m][nn][2] + bv0, acc[m][nn][3] + bv1);
            *(float2*)&y[(size_t)r0 * DOUT + c0] = v0;
            *(float2*)&y[(size_t)(r0 + 8) * DOUT + c0] = v1;
        }
    }
}

// ---------------- max over K neighbors, transposed output -------------------
__global__ void maxagg_kernel() {
    extern __shared__ unsigned char dynsm[];
    float* s = (float*)dynsm;               // [128][133]
    int n0 = blockIdx.x * 128;
    for (int idx = threadIdx.x; idx < 128 * 128; idx += 256) {
        int p = idx >> 7, c = idx & 127;
        const float* src = g_y2 + ((size_t)(n0 + p) * KNN) * 128 + c;
        float m = src[0];
#pragma unroll
        for (int j = 1; j < KNN; ++j) m = fmaxf(m, src[j * 128]);
        s[c * 133 + p] = m;
    }
    __syncthreads();
    for (int idx = threadIdx.x; idx < 128 * 128; idx += 256) {
        int c = idx >> 7, p = idx & 127;
        g_x1T[(size_t)c * NPTS + n0 + p] = s[c * 133 + p];
    }
}

// ---------------- segment max + mean pooling ----------------
__global__ void pool_kernel() {
    int b = blockIdx.x;
    int c = blockIdx.y * 128 + threadIdx.x;
    const float* p = g_x3 + (size_t)b * PPC * 1024 + c;
    float mx = -1e30f, sm = 0.f;
    for (int pt = 0; pt < PPC; ++pt) {
        float v = p[(size_t)pt * 1024];
        mx = fmaxf(mx, v); sm += v;
    }
    g_xg[b * 2048 + c] = mx;
    g_xg[b * 2048 + 1024 + c] = sm * (1.0f / 1024.0f);
}

// ---------------- layer4 ----------------
__global__ void layer4_part() {
    __shared__ float xs[2048];
    __shared__ float wsum[8][40];
    int b = blockIdx.x, sl = blockIdx.y, tid = threadIdx.x;
    for (int i = tid; i < 2048; i += 256) xs[i] = g_xg[b * 2048 + i];
    __syncthreads();
    float acc[40];
#pragma unroll
    for (int o = 0; o < 40; ++o) acc[o] = 0.f;
    for (int pp = tid; pp < 480; pp += 256) {
        int p = sl * 480 + pp;
        int w = p >> 8, i = p & 255;
        int d = (w << 7) + i;
        float ham = 0.54f - 0.46f * cosf(6.2831853071795864f * (float)i / 255.0f);
        float a = xs[d] * ham;
        float s, c; __sincosf(a, &s, &c);
        float ck = c, sk = s;
        const float* bp = g_Bp4 + p * 400;
#pragma unroll
        for (int k = 0; k < 5; ++k) {
            if (k > 0) { float cn = ck * c - sk * s, sn = sk * c + ck * s; ck = cn; sk = sn; }
            const float* c0 = bp + (2 * k) * 40;
            const float* s0 = bp + (2 * k + 1) * 40;
#pragma unroll
            for (int o = 0; o < 40; ++o) acc[o] += ck * c0[o] + sk * s0[o];
        }
    }
    int lane = tid & 31, wp = tid >> 5;
#pragma unroll
    for (int o = 0; o < 40; ++o) {
        float t = acc[o];
#pragma unroll
        for (int off = 16; off > 0; off >>= 1) t += __shfl_down_sync(0xffffffffu, t, off);
        if (lane == 0) wsum[wp][o] = t;
    }
    __syncthreads();
    if (tid < 40) {
        float t = 0.f;
#pragma unroll
        for (int w8 = 0; w8 < 8; ++w8) t += wsum[w8][tid];
        g_l4p[(b * 8 + sl) * 40 + tid] = t;
    }
}

__global__ void layer4_final(const float* __restrict__ b4, float* __restrict__ out) {
    int t = threadIdx.x;
    if (t < 320) {
        int o = t % 40;
        int b = t / 40;
        float s = b4[o];
#pragma unroll
        for (int sl = 0; sl < 8; ++sl) s += g_l4p[(b * 8 + sl) * 40 + o];
        out[t] = s;
    }
}

// ---------------- launch ----------------
extern "C" void kernel_launch(void* const* d_in, const int* in_sizes, int n_in,
                              void* d_out, int out_size) {
    (void)in_sizes; (void)n_in; (void)out_size;
    const float* pos = (const float*)d_in[0];
    const float* c1  = (const float*)d_in[2];
    const float* b1  = (const float*)d_in[3];
    const float* c2  = (const float*)d_in[4];
    const float* b2  = (const float*)d_in[5];
    const float* c3  = (const float*)d_in[6];
    const float* b3  = (const float*)d_in[7];
    const float* c4  = (const float*)d_in[8];
    const float* b4  = (const float*)d_in[9];
    float* out = (float*)d_out;

    const int SM_L1  = 80128;                 // layer1_mma
    const int SM_K   = 3 * 128 * 88 * 2;      // 67584 (Ah, Al, Bh)
    const int SM_MAX = 128 * 133 * 4;         // 68096
    cudaFuncSetAttribute(layer1_mma, cudaFuncAttributeMaxDynamicSharedMemorySize, SM_L1);
    cudaFuncSetAttribute(kan_mma<2>, cudaFuncAttributeMaxDynamicSharedMemorySize, SM_K);
    cudaFuncSetAttribute(kan_mma<3>, cudaFuncAttributeMaxDynamicSharedMemorySize, SM_K);
    cudaFuncSetAttribute(maxagg_kernel, cudaFuncAttributeMaxDynamicSharedMemorySize, SM_MAX);

    knn_kernel<<<32, 256>>>(pos);                                   // 0
    pack12<<<587, 256>>>(c1, c2);                                   // 1
    layer1_mma<<<NEDGE / 128, 256, SM_L1>>>(pos, b1);               // 2
    kan_mma<2><<<dim3(NEDGE / 128, 1), 256, SM_K>>>(b2);            // 3  <- ncu slot
    maxagg_kernel<<<NPTS / 128, 256, SM_MAX>>>();                   // 4
    pack3<<<8960, 256>>>(c3);                                       // 5
    kan_mma<3><<<dim3(NPTS / 128, 8), 256, SM_K>>>(b3);             // 6
    pack_coef4<<<6000, 256>>>(c4);                                  // 7
    pool_kernel<<<dim3(NB, 8), 128>>>();                            // 8
    layer4_part<<<dim3(NB, 8), 256>>>();                            // 9
    layer4_final<<<1, 320>>>(b4, out);                              // 10
}

// round 13
// speedup vs baseline: 1.1772x; 1.0190x over previous
#include <cuda_runtime.h>
#include <cuda_fp16.h>
#include <cstdint>

#define NB    8
#define PPC   1024
#define NPTS  8192
#define KNN   20
#define NEDGE (NPTS*KNN)

// ---------------- scratch (device globals; allocation-free) ----------------
__device__ int   g_nbr[NEDGE];
__device__ __align__(16) float g_h1T[64*NEDGE];    // layer1 out, TRANSPOSED [c][edge]
__device__ __align__(16) float g_y2[NEDGE*128];    // layer2 out (pre-max), row-major
__device__ __align__(16) float g_x1T[128*NPTS];    // after max over K, TRANSPOSED [c][n]
__device__ __align__(16) float g_x3[NPTS*1024];    // layer3 out, row-major
__device__ float g_xg[NB*2048];                    // pooled [max | mean]
__device__ __align__(16) float g_Bp4[38400*40];    // layer4 coeffs [f][o]
__device__ __align__(16) __half g_B1h[64*104];     // layer1 coeffs [o][96k pad104] hi
__device__ __align__(16) __half g_B1l[64*104];     // lo
__device__ __align__(16) __half g_B2[128*1120];    // layer2 coeffs [o][f] fp16
__device__ __align__(16) __half g_B3[1024*2240];   // layer3 coeffs [o][f] fp16
__device__ float g_l4p[NB*8*40];

// ---------------- small helpers ----------------
__device__ __forceinline__ uint32_t pack_h2(float lo, float hi) {
    __half2 h = __floats2half2_rn(lo, hi);
    return *(uint32_t*)&h;
}
__device__ __forceinline__ void mma_f16(float* c, const uint32_t* a,
                                        uint32_t b0, uint32_t b1) {
    asm volatile(
        "mma.sync.aligned.m16n8k16.row.col.f32.f16.f16.f32 "
        "{%0,%1,%2,%3}, {%4,%5,%6,%7}, {%8,%9}, {%0,%1,%2,%3};\n"
        : "+f"(c[0]), "+f"(c[1]), "+f"(c[2]), "+f"(c[3])
        : "r"(a[0]), "r"(a[1]), "r"(a[2]), "r"(a[3]), "r"(b0), "r"(b1));
}

// ---------------- packing kernels ----------------
// pack12: layer1 B (hi/lo, padded [64][104]) + layer2 B (fp16 [o][f])
__global__ void pack12(const float* __restrict__ c1, const float* __restrict__ c2) {
    int idx = blockIdx.x * 256 + threadIdx.x;
    if (idx < 64 * 104) {
        int o = idx / 104, jj = idx - o * 104;
        float v = 0.f;
        if (jj < 96) {
            int c = jj >> 4, j = jj & 15;
            if (j < 10) {
                int trig = j & 1, k = j >> 1, w = c / 3, i = c % 3;
                v = c1[(((trig * 64 + o) * 2 + w) * 3 + i) * 5 + k];
            }
        }
        __half h = __float2half_rn(v);
        g_B1h[idx] = h;
        g_B1l[idx] = __float2half_rn(v - __half2float(h));
    } else {
        int id2 = idx - 64 * 104;
        if (id2 < 128 * 1120) {
            // source-major for coalesced reads
            int k = id2 % 5, r1 = id2 / 5;
            int i = r1 % 16, r2 = r1 / 16;
            int w = r2 % 7, r3 = r2 / 7;
            int o = r3 % 128, trig = r3 / 128;
            int f = ((w * 16 + i) * 5 + k) * 2 + trig;
            g_B2[o * 1120 + f] = __float2half_rn(c2[id2]);
        }
    }
}

// source-major: consecutive threads read consecutive c3 elements
__global__ void pack3(const float* __restrict__ c3) {
    int idx = blockIdx.x * 256 + threadIdx.x;
    if (idx >= 1024 * 2240) return;
    int k = idx % 5, r1 = idx / 5;
    int i = r1 % 32, r2 = r1 / 32;
    int w = r2 % 7, r3 = r2 / 7;
    int o = r3 % 1024, trig = r3 / 1024;
    int f = ((w * 32 + i) * 5 + k) * 2 + trig;
    g_B3[(size_t)o * 2240 + f] = __float2half_rn(c3[idx]);
}

__global__ void pack_coef4(const float* __restrict__ src) {
    int idx = blockIdx.x * 256 + threadIdx.x;
    if (idx >= 38400 * 40) return;
    // source-major
    int k = idx % 5, r1 = idx / 5;
    int i = r1 % 256, r2 = r1 / 256;
    int w = r2 % 15, r3 = r2 / 15;
    int o = r3 % 40, trig = r3 / 40;
    int f = ((w * 256 + i) * 5 + k) * 2 + trig;
    g_Bp4[(size_t)f * 40 + o] = src[idx];
}

// ---------------- kNN: register top-20 per query thread ----------------
__global__ void knn_kernel(const float* __restrict__ pos) {
    __shared__ float sx[PPC], sy[PPC], sz[PPC];
    int tid = threadIdx.x;
    int b   = blockIdx.x >> 2;
    int ql  = ((blockIdx.x & 3) << 8) + tid;
    for (int p = tid; p < PPC; p += 256) {
        const float* pp = pos + (b * PPC + p) * 3;
        sx[p] = pp[0]; sy[p] = pp[1]; sz[p] = pp[2];
    }
    __syncthreads();
    float qx = sx[ql], qy = sy[ql], qz = sz[ql];
    float v[KNN]; int id[KNN];
#pragma unroll
    for (int j = 0; j < KNN; ++j) { v[j] = 1e30f; id[j] = -1; }
    float vmax = 1e30f; int mpos = 0;
    for (int p = 0; p < PPC; ++p) {
        float dx = sx[p] - qx, dy = sy[p] - qy, dz = sz[p] - qz;
        float d = dx * dx + dy * dy + dz * dz;
        if (p == ql) d = 1e30f;
        if (d < vmax) {
#pragma unroll
            for (int j = 0; j < KNN; ++j) if (j == mpos) { v[j] = d; id[j] = p; }
            vmax = v[0]; mpos = 0;
#pragma unroll
            for (int j = 1; j < KNN; ++j) if (v[j] > vmax) { vmax = v[j]; mpos = j; }
        }
    }
    int q = b * PPC + ql;
#pragma unroll
    for (int j = 0; j < KNN; ++j) g_nbr[q * KNN + j] = b * PPC + id[j];
}

// ---------------- layer1 as fused-basis HMMA (fp16x3), M=128/block -----------
__global__ void __launch_bounds__(256, 2)
layer1_mma(const float* __restrict__ pos, const float* __restrict__ b1) {
    constexpr int SA1 = 104;
    extern __shared__ unsigned char smem[];
    __half* sAh = (__half*)smem;                     // 26624 B
    __half* sAl = (__half*)(smem + 26624);           // 26624 B
    __half* sBh = (__half*)(smem + 53248);           // 13312 B
    __half* sBl = (__half*)(smem + 66560);           // 13312 B
    float*  bs  = (float*)(smem + 79872);            // 256 B
    float*  tr  = (float*)smem;                      // reuse after MMA

    int tid = threadIdx.x, lane = tid & 31, warp = tid >> 5;
    int wm = warp & 3, wn = warp >> 2;
    int qr = lane >> 2, qk = lane & 3;
    int row = tid & 127, cg = tid >> 7;

    if (tid >= 128) {
        int tt = tid - 128, str = tt >> 6, r = tt & 63;
        const uint4* src = (const uint4*)((str ? g_B1l : g_B1h) + r * 104);
        uint4* dst = (uint4*)((str ? sBl : sBh) + r * 104);
#pragma unroll
        for (int q = 0; q < 13; ++q) dst[q] = src[q];
    }
    if (tid < 64) bs[tid] = b1[tid];

    int edge = blockIdx.x * 128 + row;
    int n = edge / KNN;
    int pj = g_nbr[edge];
    float e[6];
    {
        const float* Pi = pos + n * 3;
        const float* Pj = pos + pj * 3;
        e[0] = Pi[0]; e[1] = Pi[1]; e[2] = Pi[2];
        e[3] = Pj[0] - Pi[0]; e[4] = Pj[1] - Pi[1]; e[5] = Pj[2] - Pi[2];
    }
#pragma unroll
    for (int cc = 0; cc < 3; ++cc) {
        int cl = cg * 3 + cc;
        int i = cl % 3;
        float ham = (i == 1) ? 1.0f : 0.08f;   // hamming, W=3
        float a = e[cl] * ham;
        float s, c; __sincosf(a, &s, &c);
        uint32_t* ph = (uint32_t*)&sAh[row * SA1 + cl * 16];
        uint32_t* pl = (uint32_t*)&sAl[row * SA1 + cl * 16];
        float ck = c, sk = s;
#pragma unroll
        for (int k = 0; k < 5; ++k) {
            if (k) { float cn = ck * c - sk * s, sn = sk * c + ck * s; ck = cn; sk = sn; }
            __half chh = __float2half_rn(ck), shh = __float2half_rn(sk);
            ph[k] = pack_h2(ck, sk);
            pl[k] = pack_h2(ck - __half2float(chh), sk - __half2float(shh));
        }
        ph[5] = ph[6] = ph[7] = 0u;
        pl[5] = pl[6] = pl[7] = 0u;
    }
    __syncthreads();

    float acc[2][4][4];
#pragma unroll
    for (int m = 0; m < 2; ++m)
#pragma unroll
        for (int nf = 0; nf < 4; ++nf)
#pragma unroll
            for (int q = 0; q < 4; ++q) acc[m][nf][q] = 0.f;

#pragma unroll
    for (int ks = 0; ks < 6; ++ks) {
        int kb = ks * 16;
        uint32_t ah[2][4], al[2][4];
#pragma unroll
        for (int m = 0; m < 2; ++m) {
            int rb = (wm * 32 + m * 16 + qr) * SA1 + kb + qk * 2;
            ah[m][0] = *(const uint32_t*)&sAh[rb];
            ah[m][1] = *(const uint32_t*)&sAh[rb + 8 * SA1];
            ah[m][2] = *(const uint32_t*)&sAh[rb + 8];
            ah[m][3] = *(const uint32_t*)&sAh[rb + 8 * SA1 + 8];
            al[m][0] = *(const uint32_t*)&sAl[rb];
            al[m][1] = *(const uint32_t*)&sAl[rb + 8 * SA1];
            al[m][2] = *(const uint32_t*)&sAl[rb + 8];
            al[m][3] = *(const uint32_t*)&sAl[rb + 8 * SA1 + 8];
        }
#pragma unroll
        for (int nf = 0; nf < 4; ++nf) {
            int bb = (wn * 32 + nf * 8 + qr) * SA1 + kb + qk * 2;
            uint32_t bh0 = *(const uint32_t*)&sBh[bb];
            uint32_t bh1 = *(const uint32_t*)&sBh[bb + 8];
            uint32_t bl0 = *(const uint32_t*)&sBl[bb];
            uint32_t bl1 = *(const uint32_t*)&sBl[bb + 8];
#pragma unroll
            for (int m = 0; m < 2; ++m) {
                mma_f16(acc[m][nf], ah[m], bh0, bh1);
                mma_f16(acc[m][nf], al[m], bh0, bh1);
                mma_f16(acc[m][nf], ah[m], bl0, bl1);
            }
        }
    }
    __syncthreads();   // done reading A/B smem; reuse as transpose buffer

#pragma unroll
    for (int m = 0; m < 2; ++m) {
        int r0 = wm * 32 + m * 16 + qr;
#pragma unroll
        for (int nf = 0; nf < 4; ++nf) {
            int c0 = wn * 32 + nf * 8 + qk * 2;
            tr[c0 * 132 + r0]           = acc[m][nf][0];
            tr[(c0 + 1) * 132 + r0]     = acc[m][nf][1];
            tr[c0 * 132 + r0 + 8]       = acc[m][nf][2];
            tr[(c0 + 1) * 132 + r0 + 8] = acc[m][nf][3];
        }
    }
    __syncthreads();
    int e0 = blockIdx.x * 128;
    for (int idx = tid; idx < 64 * 128; idx += 256) {
        int o = idx >> 7, r = idx & 127;
        g_h1T[(size_t)o * NEDGE + e0 + r] = tr[o * 132 + r] + bs[o];
    }
}

// ---------------- fp16x2 fused-basis GEMM (layers 2,3), scalar-LDS path -----
// LAYER==2: 256 thr, tile 128x128, grid (1280,1)
// LAYER==3: 512 thr, tile 128x256, grid (64,4)  -> basis dup x4 instead of x8
template<int LAYER>
__global__ void __launch_bounds__((LAYER == 2) ? 256 : 512, (LAYER == 2) ? 2 : 1)
kan_mma(const float* __restrict__ bias) {
    constexpr int W    = (LAYER == 2) ? 16 : 32;
    constexpr int S    = (LAYER == 2) ? 8  : 16;
    constexpr int DOUT = (LAYER == 2) ? 128 : 1024;
    constexpr int M    = (LAYER == 2) ? NEDGE : NPTS;
    constexpr int NCH  = (LAYER == 2) ? 14 : 28;
    constexpr int KTOT = (LAYER == 2) ? 1120 : 2240;
    constexpr int NT   = (LAYER == 2) ? 128 : 256;   // n-cols per block
    constexpr int PC   = (LAYER == 2) ? 4 : 2;       // producer cols/thread
    constexpr int SA   = 88;                          // padded k-stride (fp16)

    extern __shared__ unsigned char dynsm[];
    __half* sAh = (__half*)dynsm;
    __half* sAl = sAh + 128 * SA;
    __half* sBh = sAl + 128 * SA;

    const float* x = (LAYER == 2) ? g_h1T : g_x1T;   // [d][M]
    const __half* Bg = (LAYER == 2) ? g_B2 : g_B3;
    float* y = (LAYER == 2) ? g_y2 : g_x3;

    int m0 = blockIdx.x * 128;
    int n0 = blockIdx.y * NT;
    int tid = threadIdx.x;
    int lane = tid & 31, warp = tid >> 5;
    int wm = warp & 3, wn = warp >> 2;   // warp tile: 32 rows x 64 cols
    int qr = lane >> 2, qk = lane & 3;
    int row = tid & 127, cg = tid >> 7;  // producer mapping

    float acc[2][8][4];
#pragma unroll
    for (int m = 0; m < 2; ++m)
#pragma unroll
        for (int nn = 0; nn < 8; ++nn)
#pragma unroll
            for (int q = 0; q < 4; ++q) acc[m][nn][q] = 0.f;

    for (int ch = 0; ch < NCH; ++ch) {
        __syncthreads();
        // ---- produce A: 128 rows x 8 cols, PC cols per thread ----
#pragma unroll
        for (int cc = 0; cc < PC; ++cc) {
            int cl = cg * PC + cc;           // col 0..7 within chunk
            int col = ch * 8 + cl;
            int w = col / W, i = col - w * W;
            float ham = 0.54f - 0.46f * cosf(6.2831853071795864f * (float)i / (float)(W - 1));
            float a = x[(size_t)(w * S + i) * M + m0 + row] * ham;
            float s, c; __sincosf(a, &s, &c);
            float ck = c, sk = s;
            uint32_t* ph = (uint32_t*)&sAh[row * SA + cl * 10];
            uint32_t* pl = (uint32_t*)&sAl[row * SA + cl * 10];
#pragma unroll
            for (int k = 0; k < 5; ++k) {
                if (k > 0) { float cn = ck * c - sk * s, sn = sk * c + ck * s; ck = cn; sk = sn; }
                __half chh = __float2half_rn(ck);
                __half shh = __float2half_rn(sk);
                ph[k] = pack_h2(ck, sk);
                pl[k] = pack_h2(ck - __half2float(chh), sk - __half2float(shh));
            }
        }
        // ---- stage B: NT rows, one per thread (80 fp16 = 10 uint4) ----
        if (tid < NT) {
            const uint4* gb = (const uint4*)(Bg + (size_t)(n0 + tid) * KTOT + ch * 80);
            uint4* sp = (uint4*)(sBh + tid * SA);
#pragma unroll
            for (int q = 0; q < 10; ++q) sp[q] = gb[q];
        }
        __syncthreads();

#pragma unroll
        for (int ks = 0; ks < 5; ++ks) {
            int kb = ks * 16;
            uint32_t ah[2][4], al[2][4];
#pragma unroll
            for (int m = 0; m < 2; ++m) {
                int rb = (wm * 32 + m * 16 + qr) * SA + kb + qk * 2;
                ah[m][0] = *(const uint32_t*)&sAh[rb];
                ah[m][1] = *(const uint32_t*)&sAh[rb + 8 * SA];
                ah[m][2] = *(const uint32_t*)&sAh[rb + 8];
                ah[m][3] = *(const uint32_t*)&sAh[rb + 8 * SA + 8];
                al[m][0] = *(const uint32_t*)&sAl[rb];
                al[m][1] = *(const uint32_t*)&sAl[rb + 8 * SA];
                al[m][2] = *(const uint32_t*)&sAl[rb + 8];
                al[m][3] = *(const uint32_t*)&sAl[rb + 8 * SA + 8];
            }
#pragma unroll
            for (int nn = 0; nn < 8; ++nn) {
                int bb = (wn * 64 + nn * 8 + qr) * SA + kb + qk * 2;
                uint32_t bh0 = *(const uint32_t*)&sBh[bb];
                uint32_t bh1 = *(const uint32_t*)&sBh[bb + 8];
#pragma unroll
                for (int m = 0; m < 2; ++m) {
                    mma_f16(acc[m][nn], ah[m], bh0, bh1);
                    mma_f16(acc[m][nn], al[m], bh0, bh1);
                }
            }
        }
    }

    // epilogue
#pragma unroll
    for (int m = 0; m < 2; ++m) {
        int r0 = m0 + wm * 32 + m * 16 + qr;
#pragma unroll
        for (int nn = 0; nn < 8; ++nn) {
            int c0 = n0 + wn * 64 + nn * 8 + qk * 2;
            float bv0 = bias[c0], bv1 = bias[c0 + 1];
            float2 v0 = make_float2(acc[m][nn][0] + bv0, acc[m][nn][1] + bv1);
            float2 v1 = make_float2(acc[m][nn][2] + bv0, acc[m][nn][3] + bv1);
            *(float2*)&y[(size_t)r0 * DOUT + c0] = v0;
            *(float2*)&y[(size_t)(r0 + 8) * DOUT + c0] = v1;
        }
    }
}

// ---------------- max over K neighbors, transposed output -------------------
__global__ void maxagg_kernel() {
    extern __shared__ unsigned char dynsm[];
    float* s = (float*)dynsm;               // [128][133]
    int n0 = blockIdx.x * 128;
    for (int idx = threadIdx.x; idx < 128 * 128; idx += 256) {
        int p = idx >> 7, c = idx & 127;
        const float* src = g_y2 + ((size_t)(n0 + p) * KNN) * 128 + c;
        float m = src[0];
#pragma unroll
        for (int j = 1; j < KNN; ++j) m = fmaxf(m, src[j * 128]);
        s[c * 133 + p] = m;
    }
    __syncthreads();
    for (int idx = threadIdx.x; idx < 128 * 128; idx += 256) {
        int c = idx >> 7, p = idx & 127;
        g_x1T[(size_t)c * NPTS + n0 + p] = s[c * 133 + p];
    }
}

// ---------------- segment max + mean pooling ----------------
__global__ void pool_kernel() {
    int b = blockIdx.x;
    int c = blockIdx.y * 128 + threadIdx.x;
    const float* p = g_x3 + (size_t)b * PPC * 1024 + c;
    float mx = -1e30f, sm = 0.f;
    for (int pt = 0; pt < PPC; ++pt) {
        float v = p[(size_t)pt * 1024];
        mx = fmaxf(mx, v); sm += v;
    }
    g_xg[b * 2048 + c] = mx;
    g_xg[b * 2048 + 1024 + c] = sm * (1.0f / 1024.0f);
}

// ---------------- layer4 (coeffs now [f][o] with f source-major packing) ----
__global__ void layer4_part() {
    __shared__ float xs[2048];
    __shared__ float wsum[8][40];
    int b = blockIdx.x, sl = blockIdx.y, tid = threadIdx.x;
    for (int i = tid; i < 2048; i += 256) xs[i] = g_xg[b * 2048 + i];
    __syncthreads();
    float acc[40];
#pragma unroll
    for (int o = 0; o < 40; ++o) acc[o] = 0.f;
    for (int pp = tid; pp < 480; pp += 256) {
        int p = sl * 480 + pp;
        int w = p >> 8, i = p & 255;
        int d = (w << 7) + i;
        float ham = 0.54f - 0.46f * cosf(6.2831853071795864f * (float)i / 255.0f);
        float a = xs[d] * ham;
        float s, c; __sincosf(a, &s, &c);
        float ck = c, sk = s;
        const float* bp = g_Bp4 + (size_t)p * 400;
#pragma unroll
        for (int k = 0; k < 5; ++k) {
            if (k > 0) { float cn = ck * c - sk * s, sn = sk * c + ck * s; ck = cn; sk = sn; }
            const float* c0 = bp + (2 * k) * 40;
            const float* s0 = bp + (2 * k + 1) * 40;
#pragma unroll
            for (int o = 0; o < 40; ++o) acc[o] += ck * c0[o] + sk * s0[o];
        }
    }
    int lane = tid & 31, wp = tid >> 5;
#pragma unroll
    for (int o = 0; o < 40; ++o) {
        float t = acc[o];
#pragma unroll
        for (int off = 16; off > 0; off >>= 1) t += __shfl_down_sync(0xffffffffu, t, off);
        if (lane == 0) wsum[wp][o] = t;
    }
    __syncthreads();
    if (tid < 40) {
        float t = 0.f;
#pragma unroll
        for (int w8 = 0; w8 < 8; ++w8) t += wsum[w8][tid];
        g_l4p[(b * 8 + sl) * 40 + tid] = t;
    }
}

__global__ void layer4_final(const float* __restrict__ b4, float* __restrict__ out) {
    int t = threadIdx.x;
    if (t < 320) {
        int o = t % 40;
        int b = t / 40;
        float s = b4[o];
#pragma unroll
        for (int sl = 0; sl < 8; ++sl) s += g_l4p[(b * 8 + sl) * 40 + o];
        out[t] = s;
    }
}

// ---------------- launch ----------------
extern "C" void kernel_launch(void* const* d_in, const int* in_sizes, int n_in,
                              void* d_out, int out_size) {
    (void)in_sizes; (void)n_in; (void)out_size;
    const float* pos = (const float*)d_in[0];
    const float* c1  = (const float*)d_in[2];
    const float* b1  = (const float*)d_in[3];
    const float* c2  = (const float*)d_in[4];
    const float* b2  = (const float*)d_in[5];
    const float* c3  = (const float*)d_in[6];
    const float* b3  = (const float*)d_in[7];
    const float* c4  = (const float*)d_in[8];
    const float* b4  = (const float*)d_in[9];
    float* out = (float*)d_out;

    const int SM_L1  = 80128;                 // layer1_mma
    const int SM_K2  = (128 + 128 + 128) * 88 * 2;   // 67584
    const int SM_K3  = (128 + 128 + 256) * 88 * 2;   // 90112
    const int SM_MAX = 128 * 133 * 4;         // 68096
    cudaFuncSetAttribute(layer1_mma, cudaFuncAttributeMaxDynamicSharedMemorySize, SM_L1);
    cudaFuncSetAttribute(kan_mma<2>, cudaFuncAttributeMaxDynamicSharedMemorySize, SM_K2);
    cudaFuncSetAttribute(kan_mma<3>, cudaFuncAttributeMaxDynamicSharedMemorySize, SM_K3);
    cudaFuncSetAttribute(maxagg_kernel, cudaFuncAttributeMaxDynamicSharedMemorySize, SM_MAX);

    knn_kernel<<<32, 256>>>(pos);                                   // 0
    pack12<<<587, 256>>>(c1, c2);                                   // 1
    layer1_mma<<<NEDGE / 128, 256, SM_L1>>>(pos, b1);               // 2
    kan_mma<2><<<dim3(NEDGE / 128, 1), 256, SM_K2>>>(b2);           // 3  <- ncu slot
    maxagg_kernel<<<NPTS / 128, 256, SM_MAX>>>();                   // 4
    pack3<<<8960, 256>>>(c3);                                       // 5
    kan_mma<3><<<dim3(NPTS / 128, 4), 512, SM_K3>>>(b3);            // 6
    pack_coef4<<<6000, 256>>>(c4);                                  // 7
    pool_kernel<<<dim3(NB, 8), 128>>>();                            // 8
    layer4_part<<<dim3(NB, 8), 256>>>();                            // 9
    layer4_final<<<1, 320>>>(b4, out);                              // 10
}

// round 14
// speedup vs baseline: 1.2956x; 1.1006x over previous
#include <cuda_runtime.h>
#include <cuda_fp16.h>
#include <cstdint>

#define NB    8
#define PPC   1024
#define NPTS  8192
#define KNN   20
#define NEDGE (NPTS*KNN)

// ---------------- scratch (device globals; allocation-free) ----------------
__device__ int   g_nbr[NEDGE];
__device__ __align__(16) float g_h1T[64*NEDGE];    // layer1 out, TRANSPOSED [c][edge]
__device__ __align__(16) unsigned g_x1m[128*NPTS]; // max-aggregated, mono-encoded [c][n]
__device__ __align__(16) float g_x3[NPTS*1024];    // layer3 out, row-major
__device__ float g_xg[NB*2048];                    // pooled [max | mean]
__device__ __align__(16) float g_Bp4[38400*40];    // layer4 coeffs [f][o]
__device__ __align__(16) __half g_B1h[64*104];     // layer1 coeffs [o][96k pad104] hi
__device__ __align__(16) __half g_B1l[64*104];     // lo
__device__ __align__(16) __half g_B2[128*1120];    // layer2 coeffs [o][f] fp16
__device__ __align__(16) __half g_B3[1024*2240];   // layer3 coeffs [o][f] fp16
__device__ float g_l4p[NB*8*40];

// ---------------- small helpers ----------------
__device__ __forceinline__ uint32_t pack_h2(float lo, float hi) {
    __half2 h = __floats2half2_rn(lo, hi);
    return *(uint32_t*)&h;
}
__device__ __forceinline__ void mma_f16(float* c, const uint32_t* a,
                                        uint32_t b0, uint32_t b1) {
    asm volatile(
        "mma.sync.aligned.m16n8k16.row.col.f32.f16.f16.f32 "
        "{%0,%1,%2,%3}, {%4,%5,%6,%7}, {%8,%9}, {%0,%1,%2,%3};\n"
        : "+f"(c[0]), "+f"(c[1]), "+f"(c[2]), "+f"(c[3])
        : "r"(a[0]), "r"(a[1]), "r"(a[2]), "r"(a[3]), "r"(b0), "r"(b1));
}
__device__ __forceinline__ void cp16(uint32_t dst, const void* src) {
    asm volatile("cp.async.cg.shared.global [%0], [%1], 16;" :: "r"(dst), "l"(src));
}
#define CP_COMMIT() asm volatile("cp.async.commit_group;" ::: "memory")
#define CP_WAIT0()  asm volatile("cp.async.wait_group 0;" ::: "memory")

// monotonic float <-> uint mapping (order-preserving under unsigned compare)
__device__ __forceinline__ unsigned fmono(float x) {
    unsigned u = __float_as_uint(x);
    return ((int)u >= 0) ? (u | 0x80000000u) : ~u;
}
__device__ __forceinline__ float fmono_inv(unsigned m) {
    return (m & 0x80000000u) ? __uint_as_float(m & 0x7fffffffu)
                             : __uint_as_float(~m);
}
#define MONO_NEG_INF 0x007fffffu

// ---------------- packing kernels ----------------
// pack12: layer1 B (hi/lo) + layer2 B (fp16 [o][f]) + init g_x1m
__global__ void pack12(const float* __restrict__ c1, const float* __restrict__ c2) {
    int idx = blockIdx.x * 256 + threadIdx.x;
    if (idx < 64 * 104) {
        int o = idx / 104, jj = idx - o * 104;
        float v = 0.f;
        if (jj < 96) {
            int c = jj >> 4, j = jj & 15;
            if (j < 10) {
                int trig = j & 1, k = j >> 1, w = c / 3, i = c % 3;
                v = c1[(((trig * 64 + o) * 2 + w) * 3 + i) * 5 + k];
            }
        }
        __half h = __float2half_rn(v);
        g_B1h[idx] = h;
        g_B1l[idx] = __float2half_rn(v - __half2float(h));
    } else if (idx < 64 * 104 + 128 * 1120) {
        int id2 = idx - 64 * 104;
        // source-major for coalesced reads
        int k = id2 % 5, r1 = id2 / 5;
        int i = r1 % 16, r2 = r1 / 16;
        int w = r2 % 7, r3 = r2 / 7;
        int o = r3 % 128, trig = r3 / 128;
        int f = ((w * 16 + i) * 5 + k) * 2 + trig;
        g_B2[o * 1120 + f] = __float2half_rn(c2[id2]);
    } else {
        int id3 = idx - (64 * 104 + 128 * 1120);
        if (id3 < 128 * NPTS) g_x1m[id3] = MONO_NEG_INF;
    }
}

// source-major: consecutive threads read consecutive c3 elements
__global__ void pack3(const float* __restrict__ c3) {
    int idx = blockIdx.x * 256 + threadIdx.x;
    if (idx >= 1024 * 2240) return;
    int k = idx % 5, r1 = idx / 5;
    int i = r1 % 32, r2 = r1 / 32;
    int w = r2 % 7, r3 = r2 / 7;
    int o = r3 % 1024, trig = r3 / 1024;
    int f = ((w * 32 + i) * 5 + k) * 2 + trig;
    g_B3[(size_t)o * 2240 + f] = __float2half_rn(c3[idx]);
}

__global__ void pack_coef4(const float* __restrict__ src) {
    int idx = blockIdx.x * 256 + threadIdx.x;
    if (idx >= 38400 * 40) return;
    int k = idx % 5, r1 = idx / 5;
    int i = r1 % 256, r2 = r1 / 256;
    int w = r2 % 15, r3 = r2 / 15;
    int o = r3 % 40, trig = r3 / 40;
    int f = ((w * 256 + i) * 5 + k) * 2 + trig;
    g_Bp4[(size_t)f * 40 + o] = src[idx];
}

// ---------------- kNN: register top-20 per query thread ----------------
__global__ void knn_kernel(const float* __restrict__ pos) {
    __shared__ float sx[PPC], sy[PPC], sz[PPC];
    int tid = threadIdx.x;
    int b   = blockIdx.x >> 2;
    int ql  = ((blockIdx.x & 3) << 8) + tid;
    for (int p = tid; p < PPC; p += 256) {
        const float* pp = pos + (b * PPC + p) * 3;
        sx[p] = pp[0]; sy[p] = pp[1]; sz[p] = pp[2];
    }
    __syncthreads();
    float qx = sx[ql], qy = sy[ql], qz = sz[ql];
    float v[KNN]; int id[KNN];
#pragma unroll
    for (int j = 0; j < KNN; ++j) { v[j] = 1e30f; id[j] = -1; }
    float vmax = 1e30f; int mpos = 0;
    for (int p = 0; p < PPC; ++p) {
        float dx = sx[p] - qx, dy = sy[p] - qy, dz = sz[p] - qz;
        float d = dx * dx + dy * dy + dz * dz;
        if (p == ql) d = 1e30f;
        if (d < vmax) {
#pragma unroll
            for (int j = 0; j < KNN; ++j) if (j == mpos) { v[j] = d; id[j] = p; }
            vmax = v[0]; mpos = 0;
#pragma unroll
            for (int j = 1; j < KNN; ++j) if (v[j] > vmax) { vmax = v[j]; mpos = j; }
        }
    }
    int q = b * PPC + ql;
#pragma unroll
    for (int j = 0; j < KNN; ++j) g_nbr[q * KNN + j] = b * PPC + id[j];
}

// ---------------- layer1 as fused-basis HMMA (fp16x3), M=128/block -----------
__global__ void __launch_bounds__(256, 2)
layer1_mma(const float* __restrict__ pos, const float* __restrict__ b1) {
    constexpr int SA1 = 104;
    extern __shared__ unsigned char smem[];
    __half* sAh = (__half*)smem;                     // 26624 B
    __half* sAl = (__half*)(smem + 26624);           // 26624 B
    __half* sBh = (__half*)(smem + 53248);           // 13312 B
    __half* sBl = (__half*)(smem + 66560);           // 13312 B
    float*  bs  = (float*)(smem + 79872);            // 256 B
    float*  tr  = (float*)smem;                      // reuse after MMA

    int tid = threadIdx.x, lane = tid & 31, warp = tid >> 5;
    int wm = warp & 3, wn = warp >> 2;
    int qr = lane >> 2, qk = lane & 3;
    int row = tid & 127, cg = tid >> 7;

    if (tid >= 128) {
        int tt = tid - 128, str = tt >> 6, r = tt & 63;
        const uint4* src = (const uint4*)((str ? g_B1l : g_B1h) + r * 104);
        uint4* dst = (uint4*)((str ? sBl : sBh) + r * 104);
#pragma unroll
        for (int q = 0; q < 13; ++q) dst[q] = src[q];
    }
    if (tid < 64) bs[tid] = b1[tid];

    int edge = blockIdx.x * 128 + row;
    int n = edge / KNN;
    int pj = g_nbr[edge];
    float e[6];
    {
        const float* Pi = pos + n * 3;
        const float* Pj = pos + pj * 3;
        e[0] = Pi[0]; e[1] = Pi[1]; e[2] = Pi[2];
        e[3] = Pj[0] - Pi[0]; e[4] = Pj[1] - Pi[1]; e[5] = Pj[2] - Pi[2];
    }
#pragma unroll
    for (int cc = 0; cc < 3; ++cc) {
        int cl = cg * 3 + cc;
        int i = cl % 3;
        float ham = (i == 1) ? 1.0f : 0.08f;   // hamming, W=3
        float a = e[cl] * ham;
        float s, c; __sincosf(a, &s, &c);
        uint32_t* ph = (uint32_t*)&sAh[row * SA1 + cl * 16];
        uint32_t* pl = (uint32_t*)&sAl[row * SA1 + cl * 16];
        float ck = c, sk = s;
#pragma unroll
        for (int k = 0; k < 5; ++k) {
            if (k) { float cn = ck * c - sk * s, sn = sk * c + ck * s; ck = cn; sk = sn; }
            __half chh = __float2half_rn(ck), shh = __float2half_rn(sk);
            ph[k] = pack_h2(ck, sk);
            pl[k] = pack_h2(ck - __half2float(chh), sk - __half2float(shh));
        }
        ph[5] = ph[6] = ph[7] = 0u;
        pl[5] = pl[6] = pl[7] = 0u;
    }
    __syncthreads();

    float acc[2][4][4];
#pragma unroll
    for (int m = 0; m < 2; ++m)
#pragma unroll
        for (int nf = 0; nf < 4; ++nf)
#pragma unroll
            for (int q = 0; q < 4; ++q) acc[m][nf][q] = 0.f;

#pragma unroll
    for (int ks = 0; ks < 6; ++ks) {
        int kb = ks * 16;
        uint32_t ah[2][4], al[2][4];
#pragma unroll
        for (int m = 0; m < 2; ++m) {
            int rb = (wm * 32 + m * 16 + qr) * SA1 + kb + qk * 2;
            ah[m][0] = *(const uint32_t*)&sAh[rb];
            ah[m][1] = *(const uint32_t*)&sAh[rb + 8 * SA1];
            ah[m][2] = *(const uint32_t*)&sAh[rb + 8];
            ah[m][3] = *(const uint32_t*)&sAh[rb + 8 * SA1 + 8];
            al[m][0] = *(const uint32_t*)&sAl[rb];
            al[m][1] = *(const uint32_t*)&sAl[rb + 8 * SA1];
            al[m][2] = *(const uint32_t*)&sAl[rb + 8];
            al[m][3] = *(const uint32_t*)&sAl[rb + 8 * SA1 + 8];
        }
#pragma unroll
        for (int nf = 0; nf < 4; ++nf) {
            int bb = (wn * 32 + nf * 8 + qr) * SA1 + kb + qk * 2;
            uint32_t bh0 = *(const uint32_t*)&sBh[bb];
            uint32_t bh1 = *(const uint32_t*)&sBh[bb + 8];
            uint32_t bl0 = *(const uint32_t*)&sBl[bb];
            uint32_t bl1 = *(const uint32_t*)&sBl[bb + 8];
#pragma unroll
            for (int m = 0; m < 2; ++m) {
                mma_f16(acc[m][nf], ah[m], bh0, bh1);
                mma_f16(acc[m][nf], al[m], bh0, bh1);
                mma_f16(acc[m][nf], ah[m], bl0, bl1);
            }
        }
    }
    __syncthreads();   // done reading A/B smem; reuse as transpose buffer

#pragma unroll
    for (int m = 0; m < 2; ++m) {
        int r0 = wm * 32 + m * 16 + qr;
#pragma unroll
        for (int nf = 0; nf < 4; ++nf) {
            int c0 = wn * 32 + nf * 8 + qk * 2;
            tr[c0 * 132 + r0]           = acc[m][nf][0];
            tr[(c0 + 1) * 132 + r0]     = acc[m][nf][1];
            tr[c0 * 132 + r0 + 8]       = acc[m][nf][2];
            tr[(c0 + 1) * 132 + r0 + 8] = acc[m][nf][3];
        }
    }
    __syncthreads();
    int e0 = blockIdx.x * 128;
    for (int idx = tid; idx < 64 * 128; idx += 256) {
        int o = idx >> 7, r = idx & 127;
        g_h1T[(size_t)o * NEDGE + e0 + r] = tr[o * 132 + r] + bs[o];
    }
}

// ---------------- fp16x2 fused-basis GEMM, pipelined loads ------------------
// LAYER==2: 256 thr, tile 128x128; fused K-neighbor max epilogue (atomicMax mono)
// LAYER==3: 512 thr, tile 128x256; reads mono-encoded x1m, writes g_x3
template<int LAYER>
__global__ void __launch_bounds__((LAYER == 2) ? 256 : 512, (LAYER == 2) ? 2 : 1)
kan_mma(const float* __restrict__ bias) {
    constexpr int W    = (LAYER == 2) ? 16 : 32;
    constexpr int S    = (LAYER == 2) ? 8  : 16;
    constexpr int DOUT = (LAYER == 2) ? 128 : 1024;
    constexpr int M    = (LAYER == 2) ? NEDGE : NPTS;
    constexpr int NCH  = (LAYER == 2) ? 14 : 28;
    constexpr int KTOT = (LAYER == 2) ? 1120 : 2240;
    constexpr int NT   = (LAYER == 2) ? 128 : 256;   // n-cols per block
    constexpr int PC   = (LAYER == 2) ? 4 : 2;       // producer cols/thread
    constexpr int SA   = 88;                          // padded k-stride (fp16)
    constexpr uint32_t ABY = 128u * SA * 2;           // 22528
    constexpr uint32_t BBY = (uint32_t)NT * SA * 2;   // 22528 / 45056

    extern __shared__ unsigned char dynsm[];
    __half* sAh = (__half*)dynsm;
    __half* sAl = (__half*)(dynsm + ABY);
    uint32_t smem_b = (uint32_t)__cvta_generic_to_shared(dynsm);

    const unsigned* xsrc = (LAYER == 2) ? (const unsigned*)g_h1T : g_x1m;
    const __half* Bg = (LAYER == 2) ? g_B2 : g_B3;

    int m0 = blockIdx.x * 128;
    int n0 = blockIdx.y * NT;
    int tid = threadIdx.x;
    int lane = tid & 31, warp = tid >> 5;
    int wm = warp & 3, wn = warp >> 2;   // warp tile: 32 rows x 64 cols
    int qr = lane >> 2, qk = lane & 3;
    int row = tid & 127, cg = tid >> 7;  // producer mapping

    float acc[2][8][4];
#pragma unroll
    for (int m = 0; m < 2; ++m)
#pragma unroll
        for (int nn = 0; nn < 8; ++nn)
#pragma unroll
            for (int q = 0; q < 4; ++q) acc[m][nn][q] = 0.f;

    unsigned xv[PC], xn[PC];

    auto ldx = [&](int ch, unsigned* d) {
#pragma unroll
        for (int cc = 0; cc < PC; ++cc) {
            int cl = cg * PC + cc, col = ch * 8 + cl;
            int w = col / W, i = col - w * W;
            d[cc] = xsrc[(size_t)(w * S + i) * M + m0 + row];
        }
    };
    auto storeA = [&](int ch) {
#pragma unroll
        for (int cc = 0; cc < PC; ++cc) {
            int cl = cg * PC + cc, col = ch * 8 + cl;
            int w = col / W, i = col - w * W;
            float ham = 0.54f - 0.46f * cosf(6.2831853071795864f * (float)i / (float)(W - 1));
            float xf = (LAYER == 2) ? __uint_as_float(xv[cc]) : fmono_inv(xv[cc]);
            float a = xf * ham;
            float s, c; __sincosf(a, &s, &c);
            float ck = c, sk = s;
            uint32_t* ph = (uint32_t*)&sAh[row * SA + cl * 10];
            uint32_t* pl = (uint32_t*)&sAl[row * SA + cl * 10];
#pragma unroll
            for (int k = 0; k < 5; ++k) {
                if (k > 0) { float cn = ck * c - sk * s, sn = sk * c + ck * s; ck = cn; sk = sn; }
                __half chh = __float2half_rn(ck);
                __half shh = __float2half_rn(sk);
                ph[k] = pack_h2(ck, sk);
                pl[k] = pack_h2(ck - __half2float(chh), sk - __half2float(shh));
            }
        }
    };
    auto cpB = [&](int ch, int b) {
        if (tid < NT) {
            const __half* src = Bg + (size_t)(n0 + tid) * KTOT + ch * 80;
            uint32_t dst = smem_b + 2 * ABY + (uint32_t)b * BBY + (uint32_t)tid * (SA * 2);
#pragma unroll
            for (int q = 0; q < 10; ++q) cp16(dst + q * 16, src + q * 8);
        }
        CP_COMMIT();
    };

    ldx(0, xv);
    cpB(0, 0);
    for (int ch = 0; ch < NCH; ++ch) {
        __syncthreads();                       // all warps done reading A(ch-1)
        storeA(ch);                            // MUFU + STS, no LDG stall
        if (ch + 1 < NCH) ldx(ch + 1, xn);     // prefetch x for next chunk
        CP_WAIT0();                            // B(ch) landed
        __syncthreads();                       // A + B visible to all
        if (ch + 1 < NCH) cpB(ch + 1, (ch + 1) & 1);   // async during MMA
        const __half* sBh = (const __half*)(dynsm + 2 * ABY + (uint32_t)(ch & 1) * BBY);

#pragma unroll
        for (int ks = 0; ks < 5; ++ks) {
            int kb = ks * 16;
            uint32_t ah[2][4], al[2][4];
#pragma unroll
            for (int m = 0; m < 2; ++m) {
                int rb = (wm * 32 + m * 16 + qr) * SA + kb + qk * 2;
                ah[m][0] = *(const uint32_t*)&sAh[rb];
                ah[m][1] = *(const uint32_t*)&sAh[rb + 8 * SA];
                ah[m][2] = *(const uint32_t*)&sAh[rb + 8];
                ah[m][3] = *(const uint32_t*)&sAh[rb + 8 * SA + 8];
                al[m][0] = *(const uint32_t*)&sAl[rb];
                al[m][1] = *(const uint32_t*)&sAl[rb + 8 * SA];
                al[m][2] = *(const uint32_t*)&sAl[rb + 8];
                al[m][3] = *(const uint32_t*)&sAl[rb + 8 * SA + 8];
            }
#pragma unroll
            for (int nn = 0; nn < 8; ++nn) {
                int bb = (wn * 64 + nn * 8 + qr) * SA + kb + qk * 2;
                uint32_t bh0 = *(const uint32_t*)&sBh[bb];
                uint32_t bh1 = *(const uint32_t*)&sBh[bb + 8];
#pragma unroll
                for (int m = 0; m < 2; ++m) {
                    mma_f16(acc[m][nn], ah[m], bh0, bh1);
                    mma_f16(acc[m][nn], al[m], bh0, bh1);
                }
            }
        }
#pragma unroll
        for (int cc = 0; cc < PC; ++cc) xv[cc] = xn[cc];
    }
    __syncthreads();   // all MMA done; smem reusable

    if constexpr (LAYER == 2) {
        // fused K-neighbor max epilogue
        float* ep = (float*)dynsm;             // [128 rows][132]
#pragma unroll
        for (int m = 0; m < 2; ++m) {
            int r0 = wm * 32 + m * 16 + qr;
#pragma unroll
            for (int nn = 0; nn < 8; ++nn) {
                int c0 = wn * 64 + nn * 8 + qk * 2;
                float bv0 = bias[n0 + c0], bv1 = bias[n0 + c0 + 1];
                ep[r0 * 132 + c0]           = acc[m][nn][0] + bv0;
                ep[r0 * 132 + c0 + 1]       = acc[m][nn][1] + bv1;
                ep[(r0 + 8) * 132 + c0]     = acc[m][nn][2] + bv0;
                ep[(r0 + 8) * 132 + c0 + 1] = acc[m][nn][3] + bv1;
            }
        }
        __syncthreads();
        int Pstart = m0 / KNN;
        int Pend = (m0 + 127) / KNN;
        int npts = Pend - Pstart + 1;          // <= 8
        for (int e2 = tid; e2 < npts * 128; e2 += 256) {
            int lp = e2 >> 7, c = e2 & 127;
            int P = Pstart + lp;
            int r0 = max(P * KNN - m0, 0);
            int r1 = min(P * KNN + KNN - m0, 128);
            float mx = -3.4e38f;
            for (int r = r0; r < r1; ++r) mx = fmaxf(mx, ep[r * 132 + c]);
            atomicMax(&g_x1m[(size_t)c * NPTS + P], fmono(mx));
        }
    } else {
        // plain epilogue to g_x3
#pragma unroll
        for (int m = 0; m < 2; ++m) {
            int r0 = m0 + wm * 32 + m * 16 + qr;
#pragma unroll
            for (int nn = 0; nn < 8; ++nn) {
                int c0 = n0 + wn * 64 + nn * 8 + qk * 2;
                float bv0 = bias[c0], bv1 = bias[c0 + 1];
                float2 v0 = make_float2(acc[m][nn][0] + bv0, acc[m][nn][1] + bv1);
                float2 v1 = make_float2(acc[m][nn][2] + bv0, acc[m][nn][3] + bv1);
                *(float2*)&g_x3[(size_t)r0 * DOUT + c0] = v0;
                *(float2*)&g_x3[(size_t)(r0 + 8) * DOUT + c0] = v1;
            }
        }
    }
}

// ---------------- segment max + mean pooling ----------------
__global__ void pool_kernel() {
    int b = blockIdx.x;
    int c = blockIdx.y * 128 + threadIdx.x;
    const float* p = g_x3 + (size_t)b * PPC * 1024 + c;
    float mx = -1e30f, sm = 0.f;
    for (int pt = 0; pt < PPC; ++pt) {
        float v = p[(size_t)pt * 1024];
        mx = fmaxf(mx, v); sm += v;
    }
    g_xg[b * 2048 + c] = mx;
    g_xg[b * 2048 + 1024 + c] = sm * (1.0f / 1024.0f);
}

// ---------------- layer4 ----------------
__global__ void layer4_part() {
    __shared__ float xs[2048];
    __shared__ float wsum[8][40];
    int b = blockIdx.x, sl = blockIdx.y, tid = threadIdx.x;
    for (int i = tid; i < 2048; i += 256) xs[i] = g_xg[b * 2048 + i];
    __syncthreads();
    float acc[40];
#pragma unroll
    for (int o = 0; o < 40; ++o) acc[o] = 0.f;
    for (int pp = tid; pp < 480; pp += 256) {
        int p = sl * 480 + pp;
        int w = p >> 8, i = p & 255;
        int d = (w << 7) + i;
        float ham = 0.54f - 0.46f * cosf(6.2831853071795864f * (float)i / 255.0f);
        float a = xs[d] * ham;
        float s, c; __sincosf(a, &s, &c);
        float ck = c, sk = s;
        const float* bp = g_Bp4 + (size_t)p * 400;
#pragma unroll
        for (int k = 0; k < 5; ++k) {
            if (k > 0) { float cn = ck * c - sk * s, sn = sk * c + ck * s; ck = cn; sk = sn; }
            const float* c0 = bp + (2 * k) * 40;
            const float* s0 = bp + (2 * k + 1) * 40;
#pragma unroll
            for (int o = 0; o < 40; ++o) acc[o] += ck * c0[o] + sk * s0[o];
        }
    }
    int lane = tid & 31, wp = tid >> 5;
#pragma unroll
    for (int o = 0; o < 40; ++o) {
        float t = acc[o];
#pragma unroll
        for (int off = 16; off > 0; off >>= 1) t += __shfl_down_sync(0xffffffffu, t, off);
        if (lane == 0) wsum[wp][o] = t;
    }
    __syncthreads();
    if (tid < 40) {
        float t = 0.f;
#pragma unroll
        for (int w8 = 0; w8 < 8; ++w8) t += wsum[w8][tid];
        g_l4p[(b * 8 + sl) * 40 + tid] = t;
    }
}

__global__ void layer4_final(const float* __restrict__ b4, float* __restrict__ out) {
    int t = threadIdx.x;
    if (t < 320) {
        int o = t % 40;
        int b = t / 40;
        float s = b4[o];
#pragma unroll
        for (int sl = 0; sl < 8; ++sl) s += g_l4p[(b * 8 + sl) * 40 + o];
        out[t] = s;
    }
}

// ---------------- launch ----------------
extern "C" void kernel_launch(void* const* d_in, const int* in_sizes, int n_in,
                              void* d_out, int out_size) {
    (void)in_sizes; (void)n_in; (void)out_size;
    const float* pos = (const float*)d_in[0];
    const float* c1  = (const float*)d_in[2];
    const float* b1  = (const float*)d_in[3];
    const float* c2  = (const float*)d_in[4];
    const float* b2  = (const float*)d_in[5];
    const float* c3  = (const float*)d_in[6];
    const float* b3  = (const float*)d_in[7];
    const float* c4  = (const float*)d_in[8];
    const float* b4  = (const float*)d_in[9];
    float* out = (float*)d_out;

    const int SM_L1 = 80128;                          // layer1_mma
    const int SM_K2 = 2 * 22528 + 2 * 22528;          // 90112
    const int SM_K3 = 2 * 22528 + 2 * 45056;          // 135168
    cudaFuncSetAttribute(layer1_mma, cudaFuncAttributeMaxDynamicSharedMemorySize, SM_L1);
    cudaFuncSetAttribute(kan_mma<2>, cudaFuncAttributeMaxDynamicSharedMemorySize, SM_K2);
    cudaFuncSetAttribute(kan_mma<3>, cudaFuncAttributeMaxDynamicSharedMemorySize, SM_K3);

    knn_kernel<<<32, 256>>>(pos);                                   // 0
    pack12<<<4682, 256>>>(c1, c2);                                  // 1 (+x1m init)
    layer1_mma<<<NEDGE / 128, 256, SM_L1>>>(pos, b1);               // 2
    kan_mma<2><<<dim3(NEDGE / 128, 1), 256, SM_K2>>>(b2);           // 3  <- ncu slot
    pack3<<<8960, 256>>>(c3);                                       // 4
    kan_mma<3><<<dim3(NPTS / 128, 4), 512, SM_K3>>>(b3);            // 5
    pack_coef4<<<6000, 256>>>(c4);                                  // 6
    pool_kernel<<<dim3(NB, 8), 128>>>();                            // 7
    layer4_part<<<dim3(NB, 8), 256>>>();                            // 8
    layer4_final<<<1, 320>>>(b4, out);                              // 9
}